// round 13
// baseline (speedup 1.0000x reference)
#include <cuda.h>
#include <cuda_runtime.h>
#include <cuda_fp16.h>
#include <cstdint>

#define SEQ   1024
#define HID   2048
#define K2DIM 4096
#define VOC   129280
#define EPSV  1e-6f
#define NT    (VOC / 128)          // 1010 N-tiles (128-wide)

// single dynamic-smem symbol shared by all kernels
extern __shared__ char dyn_smem[];

// ---------------- scratch (device globals, no allocation) ----------------
__device__ __half g_ch[SEQ * K2DIM];                // 8 MB combined hi
__device__ __half g_cl[SEQ * K2DIM];                // 8 MB combined lo
__device__ __half g_ewh[(size_t)HID * K2DIM];       // 16 MB ehw hi
__device__ __half g_ewl[(size_t)HID * K2DIM];       // 16 MB ehw lo
__device__ float  g_proj[SEQ * HID];                // 8 MB
__device__ __half g_a16[SEQ * HID];                 // 4 MB (normed, fp16)
__device__ __half g_b16[(size_t)VOC * HID];         // 529 MB (lm_head_w fp16)
__device__ float  g_pmax[(size_t)SEQ * NT];         // [s][nt] coalesced for reduce
__device__ float  g_psum[(size_t)SEQ * NT];
__device__ float  g_nll[SEQ];

// ---------------- helpers ----------------
__device__ __forceinline__ unsigned h2_as_u32(__half2 h) {
    union { __half2 h; unsigned u; } c; c.h = h; return c.u;
}
__device__ __forceinline__ bool detect_i64(const int* w) {
    bool z = true;
#pragma unroll
    for (int j = 1; j < 32; j += 2) z = z && (w[j] == 0);
    return z;
}
__device__ __forceinline__ int load_idx(const void* p, int i, bool is64) {
    return is64 ? (int)((const long long*)p)[i] : ((const int*)p)[i];
}
__device__ __forceinline__ float block_sum256(float v, volatile float* red) {
#pragma unroll
    for (int o = 16; o > 0; o >>= 1) v += __shfl_xor_sync(0xffffffffu, v, o);
    if ((threadIdx.x & 31) == 0) red[threadIdx.x >> 5] = v;
    __syncthreads();
    float t = red[0] + red[1] + red[2] + red[3] + red[4] + red[5] + red[6] + red[7];
    __syncthreads();
    return t;
}

__device__ __forceinline__ void cp_async16(void* smem, const void* gmem) {
    unsigned sa = (unsigned)__cvta_generic_to_shared(smem);
    asm volatile("cp.async.ca.shared.global [%0], [%1], 16;" :: "r"(sa), "l"(gmem));
}
__device__ __forceinline__ void cp_commit() { asm volatile("cp.async.commit_group;"); }
__device__ __forceinline__ void cp_wait0() { asm volatile("cp.async.wait_group 0;"); }
__device__ __forceinline__ void cp_wait1() { asm volatile("cp.async.wait_group 1;"); }

__device__ __forceinline__ void ldsm_x4(uint32_t& r0, uint32_t& r1, uint32_t& r2,
                                        uint32_t& r3, uint32_t saddr) {
    asm volatile("ldmatrix.sync.aligned.m8n8.x4.shared.b16 {%0,%1,%2,%3}, [%4];"
        : "=r"(r0), "=r"(r1), "=r"(r2), "=r"(r3) : "r"(saddr));
}

__device__ __forceinline__ void mma_f16(float c[4], const uint32_t a[4], const uint32_t b[2]) {
    asm volatile(
        "mma.sync.aligned.m16n8k16.row.col.f32.f16.f16.f32 "
        "{%0,%1,%2,%3}, {%4,%5,%6,%7}, {%8,%9}, {%0,%1,%2,%3};"
        : "+f"(c[0]), "+f"(c[1]), "+f"(c[2]), "+f"(c[3])
        : "r"(a[0]), "r"(a[1]), "r"(a[2]), "r"(a[3]), "r"(b[0]), "r"(b[1]));
}

// ---------------- kernel A: gather + enorm + hnorm + concat (hi/lo fp16) ----
__global__ void __launch_bounds__(256) prep_kernel(
    const float* __restrict__ hidden, const void* __restrict__ ids,
    const float* __restrict__ embed_w, const float* __restrict__ enorm_w,
    const float* __restrict__ hnorm_w,
    __half* __restrict__ chi, __half* __restrict__ clo)
{
    __shared__ float s_e[HID];
    __shared__ float s_h[HID];
    __shared__ float red[8];
    __shared__ int s_id;
    int tid = threadIdx.x, sid = blockIdx.x;
    if (tid == 0) {
        bool is64 = detect_i64((const int*)ids);
        s_id = load_idx(ids, sid, is64);
    }
    __syncthreads();
    const float* erow = embed_w + (size_t)s_id * HID;
    const float* hrow = hidden + (size_t)sid * HID;
    float se = 0.f, sh = 0.f;
    for (int j = tid; j < HID; j += 256) {
        float e = erow[j], h = hrow[j];
        s_e[j] = e; s_h[j] = h;
        se += e * e; sh += h * h;
    }
    float vse = block_sum256(se, red);
    float vsh = block_sum256(sh, red);
    float re = rsqrtf(vse / HID + EPSV);
    float rh = rsqrtf(vsh / HID + EPSV);
    __half* oh = chi + (size_t)sid * K2DIM;
    __half* ol = clo + (size_t)sid * K2DIM;
    for (int j = tid; j < HID; j += 256) {
        float v0 = enorm_w[j] * s_e[j] * re;
        float v1 = hnorm_w[j] * s_h[j] * rh;
        __half h0 = __float2half_rn(v0);
        __half h1 = __float2half_rn(v1);
        oh[j]       = h0; ol[j]       = __float2half_rn(v0 - __half2float(h0));
        oh[HID + j] = h1; ol[HID + j] = __float2half_rn(v1 - __half2float(h1));
    }
}

// ---------------- double RMSNorm (ln then norm) -> fp16 output ----------------
__global__ void __launch_bounds__(256) norm2_kernel(
    const float* __restrict__ x, const float* __restrict__ lnw,
    const float* __restrict__ nw, __half* __restrict__ out)
{
    __shared__ float sx[HID];
    __shared__ float red[8];
    int sid = blockIdx.x, tid = threadIdx.x;
    const float* row = x + (size_t)sid * HID;
    float ss = 0.f;
    for (int j = tid; j < HID; j += 256) { float v = row[j]; sx[j] = v; ss += v * v; }
    float r1 = rsqrtf(block_sum256(ss, red) / HID + EPSV);
    float ss2 = 0.f;
    for (int j = tid; j < HID; j += 256) { float p = lnw[j] * sx[j] * r1; sx[j] = p; ss2 += p * p; }
    float r2 = rsqrtf(block_sum256(ss2, red) / HID + EPSV);
    __half* o = out + (size_t)sid * HID;
    for (int j = tid; j < HID; j += 256) o[j] = __float2half_rn(nw[j] * sx[j] * r2);
}

// ---------------- f32 -> f16 bulk convert (lm_head weights) ----------------
__global__ void __launch_bounds__(256) cvt_kernel(
    const float* __restrict__ in, __half* __restrict__ out)
{
    size_t i = ((size_t)blockIdx.x * 256 + threadIdx.x) * 8;
    float4 v0 = *reinterpret_cast<const float4*>(in + i);
    float4 v1 = *reinterpret_cast<const float4*>(in + i + 4);
    uint4 pk;
    pk.x = h2_as_u32(__floats2half2_rn(v0.x, v0.y));
    pk.y = h2_as_u32(__floats2half2_rn(v0.z, v0.w));
    pk.z = h2_as_u32(__floats2half2_rn(v1.x, v1.y));
    pk.w = h2_as_u32(__floats2half2_rn(v1.z, v1.w));
    *reinterpret_cast<uint4*>(out + i) = pk;
}

// ---------------- f32 -> (hi, lo) fp16 split convert (ehw) ----------------
__global__ void __launch_bounds__(256) cvt_split_kernel(
    const float* __restrict__ in, __half* __restrict__ hi, __half* __restrict__ lo)
{
    size_t i = ((size_t)blockIdx.x * 256 + threadIdx.x) * 8;
    float v[8];
    *reinterpret_cast<float4*>(v)     = *reinterpret_cast<const float4*>(in + i);
    *reinterpret_cast<float4*>(v + 4) = *reinterpret_cast<const float4*>(in + i + 4);
    __half h[8], l[8];
#pragma unroll
    for (int j = 0; j < 8; j++) {
        h[j] = __float2half_rn(v[j]);
        l[j] = __float2half_rn(v[j] - __half2float(h[j]));
    }
    *reinterpret_cast<uint4*>(hi + i) = *reinterpret_cast<uint4*>(h);
    *reinterpret_cast<uint4*>(lo + i) = *reinterpret_cast<uint4*>(l);
}

// =======================================================================
// eh_proj: 3-term split-fp16 GEMM (at tensor floor; unchanged from R12)
// =======================================================================
#define EH_LDK  72
#define EH_A1   (64 * EH_LDK)
#define EH_B1   (128 * EH_LDK)
#define EH_STG  (2 * EH_A1 + 2 * EH_B1)
#define EH_SMEM (2 * EH_STG * 2)          // 110592 B -> 2 CTAs/SM
#define EH_KT   (K2DIM / 64)              // 64

__device__ __forceinline__ void eh_load_stage(
    const __half* __restrict__ Ah, const __half* __restrict__ Al,
    const __half* __restrict__ Bh, const __half* __restrict__ Bl,
    __half* smem, int kt, int s, int bm, int bn, int tid)
{
    __half* st = smem + s * EH_STG;
    size_t a0 = (size_t)bm * K2DIM + kt * 64;
    size_t b0 = (size_t)bn * K2DIM + kt * 64;
#pragma unroll
    for (int i = 0; i < 2; i++) {
        int c = tid + i * 256;
        int r = c >> 3, kc = (c & 7) * 8;
        int so = r * EH_LDK + kc;
        cp_async16(st + so,          Ah + a0 + (size_t)r * K2DIM + kc);
        cp_async16(st + EH_A1 + so,  Al + a0 + (size_t)r * K2DIM + kc);
    }
#pragma unroll
    for (int i = 0; i < 4; i++) {
        int c = tid + i * 256;
        int r = c >> 3, kc = (c & 7) * 8;
        int so = r * EH_LDK + kc;
        cp_async16(st + 2 * EH_A1 + so,          Bh + b0 + (size_t)r * K2DIM + kc);
        cp_async16(st + 2 * EH_A1 + EH_B1 + so,  Bl + b0 + (size_t)r * K2DIM + kc);
    }
}

__global__ void __launch_bounds__(256, 2) eh_fp16_kernel(
    const __half* __restrict__ Ah, const __half* __restrict__ Al,
    const __half* __restrict__ Bh, const __half* __restrict__ Bl,
    float* __restrict__ C)
{
    __half* smem = (__half*)dyn_smem;
    int tid = threadIdx.x;
    int lane = tid & 31, warp = tid >> 5;
    int wm = warp & 1, wn = warp >> 1;
    int gid = lane >> 2, tig = lane & 3;
    int bm = blockIdx.x * 64;
    int bn = blockIdx.y * 128;

    float acc[2][4][4];
#pragma unroll
    for (int i = 0; i < 2; i++)
#pragma unroll
        for (int j = 0; j < 4; j++)
#pragma unroll
            for (int q = 0; q < 4; q++) acc[i][j][q] = 0.f;

    uint32_t smem_u = (uint32_t)__cvta_generic_to_shared(smem);
    int a_off = (wm * 32 + (lane & 15)) * EH_LDK + ((lane >> 4) << 3);
    int b_off = (wn * 32 + ((lane >> 4) << 3) + (lane & 7)) * EH_LDK + (((lane >> 3) & 1) << 3);

    eh_load_stage(Ah, Al, Bh, Bl, smem, 0, 0, bm, bn, tid); cp_commit();

    for (int kt = 0; kt < EH_KT; ++kt) {
        if (kt + 1 < EH_KT) {
            eh_load_stage(Ah, Al, Bh, Bl, smem, kt + 1, (kt + 1) & 1, bm, bn, tid);
            cp_commit();
            cp_wait1();
        } else {
            cp_wait0();
        }
        __syncthreads();
        uint32_t stg = (kt & 1) * EH_STG;
        uint32_t ah_base = smem_u + (stg + a_off) * 2;
        uint32_t al_base = ah_base + EH_A1 * 2;
        uint32_t bh_base = smem_u + (stg + 2 * EH_A1 + b_off) * 2;
        uint32_t bl_base = bh_base + EH_B1 * 2;
#pragma unroll
        for (int kk = 0; kk < 4; kk++) {
            uint32_t ahf[2][4], alf[2][4], bhf[2][4], blf[2][4];
#pragma unroll
            for (int mi = 0; mi < 2; mi++) {
                ldsm_x4(ahf[mi][0], ahf[mi][1], ahf[mi][2], ahf[mi][3],
                        ah_base + (mi * 16 * EH_LDK + kk * 16) * 2);
                ldsm_x4(alf[mi][0], alf[mi][1], alf[mi][2], alf[mi][3],
                        al_base + (mi * 16 * EH_LDK + kk * 16) * 2);
            }
#pragma unroll
            for (int np = 0; np < 2; np++) {
                ldsm_x4(bhf[np][0], bhf[np][1], bhf[np][2], bhf[np][3],
                        bh_base + (np * 16 * EH_LDK + kk * 16) * 2);
                ldsm_x4(blf[np][0], blf[np][1], blf[np][2], blf[np][3],
                        bl_base + (np * 16 * EH_LDK + kk * 16) * 2);
            }
#pragma unroll
            for (int mi = 0; mi < 2; mi++) {
#pragma unroll
                for (int np = 0; np < 2; np++) {
                    mma_f16(acc[mi][2 * np],     ahf[mi], &bhf[np][0]);
                    mma_f16(acc[mi][2 * np + 1], ahf[mi], &bhf[np][2]);
                    mma_f16(acc[mi][2 * np],     ahf[mi], &blf[np][0]);
                    mma_f16(acc[mi][2 * np + 1], ahf[mi], &blf[np][2]);
                    mma_f16(acc[mi][2 * np],     alf[mi], &bhf[np][0]);
                    mma_f16(acc[mi][2 * np + 1], alf[mi], &bhf[np][2]);
                }
            }
        }
        __syncthreads();
    }

    float* Cb = C + (size_t)(bm + wm * 32) * HID + bn + wn * 32;
#pragma unroll
    for (int mi = 0; mi < 2; mi++) {
#pragma unroll
        for (int ni = 0; ni < 4; ni++) {
            int r = mi * 16 + gid;
            int c = ni * 8 + tig * 2;
            float2 v0 = make_float2(acc[mi][ni][0], acc[mi][ni][1]);
            float2 v1 = make_float2(acc[mi][ni][2], acc[mi][ni][3]);
            *reinterpret_cast<float2*>(Cb + (size_t)r * HID + c) = v0;
            *reinterpret_cast<float2*>(Cb + (size_t)(r + 8) * HID + c) = v1;
        }
    }
}

// =======================================================================
// lm_head: fp16 mma.sync GEMM + fused softmax partials
//   R9 shape (128x128, 8 warps, BK=64, 3-stage, 2 CTAs/SM)
//   + B-fragment software pipeline across kk-steps.
// =======================================================================
#define LM_BM   128
#define LM_BN   128
#define LM_BK   64
#define LM_LDK  72
#define LM_ASZ  (LM_BM * LM_LDK)
#define LM_BSZ  (LM_BN * LM_LDK)
#define LM_STG  (LM_ASZ + LM_BSZ)
#define LM_SMEM (3 * LM_STG * 2)         // 110592 B
#define LM_KT   (HID / LM_BK)            // 32

__device__ __forceinline__ void lm_load_stage(
    const __half* __restrict__ A16, const __half* __restrict__ B16,
    __half* smem, int kt, int s, int bm, int bn, int tid)
{
    __half* as = smem + s * LM_STG;
    __half* bs = as + LM_ASZ;
    const __half* Ag = A16 + (size_t)bm * HID + kt * LM_BK;
    const __half* Bg = B16 + (size_t)bn * HID + kt * LM_BK;
#pragma unroll
    for (int i = 0; i < 4; i++) {
        int c = tid + i * 256;
        int r = c >> 3, kc = (c & 7) * 8;
        cp_async16(as + r * LM_LDK + kc, Ag + (size_t)r * HID + kc);
    }
#pragma unroll
    for (int i = 0; i < 4; i++) {
        int c = tid + i * 256;
        int r = c >> 3, kc = (c & 7) * 8;
        cp_async16(bs + r * LM_LDK + kc, Bg + (size_t)r * HID + kc);
    }
}

__global__ void __launch_bounds__(256, 2) lm_fp16_kernel(
    const __half* __restrict__ A16, const __half* __restrict__ B16,
    float* __restrict__ C, float* __restrict__ pmax, float* __restrict__ psum)
{
    __half* smem = (__half*)dyn_smem;
    int tid = threadIdx.x;
    int lane = tid & 31, warp = tid >> 5;
    int wm = warp & 1, wn = warp >> 1;
    int gid = lane >> 2, tig = lane & 3;
    int bm = blockIdx.x * LM_BM;
    int bn = blockIdx.y * LM_BN;

    float acc[4][4][4];
#pragma unroll
    for (int i = 0; i < 4; i++)
#pragma unroll
        for (int j = 0; j < 4; j++)
#pragma unroll
            for (int q = 0; q < 4; q++) acc[i][j][q] = 0.f;

    uint32_t smem_u = (uint32_t)__cvta_generic_to_shared(smem);
    int a_off = (wm * 64 + (lane & 15)) * LM_LDK + ((lane >> 4) << 3);
    int b_off = (wn * 32 + ((lane >> 4) << 3) + (lane & 7)) * LM_LDK + (((lane >> 3) & 1) << 3);

    lm_load_stage(A16, B16, smem, 0, 0, bm, bn, tid); cp_commit();
    lm_load_stage(A16, B16, smem, 1, 1, bm, bn, tid); cp_commit();

    for (int kt = 0; kt < LM_KT; ++kt) {
        if (kt >= LM_KT - 2) cp_wait0(); else cp_wait1();
        __syncthreads();
        if (kt + 2 < LM_KT) {
            lm_load_stage(A16, B16, smem, kt + 2, (kt + 2) % 3, bm, bn, tid);
            cp_commit();
        }
        uint32_t a_base = smem_u + ((kt % 3) * LM_STG + a_off) * 2;
        uint32_t b_base = smem_u + ((kt % 3) * LM_STG + LM_ASZ + b_off) * 2;

        // B-fragment software pipeline: load kk=0 B frags up front,
        // prefetch kk+1's B frags before issuing kk's MMAs.
        uint32_t bf_cur[2][4], bf_nxt[2][4];
#pragma unroll
        for (int np = 0; np < 2; np++)
            ldsm_x4(bf_cur[np][0], bf_cur[np][1], bf_cur[np][2], bf_cur[np][3],
                    b_base + (np * 16 * LM_LDK) * 2);
#pragma unroll
        for (int kk = 0; kk < 4; kk++) {
            if (kk < 3) {
#pragma unroll
                for (int np = 0; np < 2; np++)
                    ldsm_x4(bf_nxt[np][0], bf_nxt[np][1], bf_nxt[np][2], bf_nxt[np][3],
                            b_base + (np * 16 * LM_LDK + (kk + 1) * 16) * 2);
            }
            uint32_t af[4][4];
#pragma unroll
            for (int mi = 0; mi < 4; mi++)
                ldsm_x4(af[mi][0], af[mi][1], af[mi][2], af[mi][3],
                        a_base + (mi * 16 * LM_LDK + kk * 16) * 2);
#pragma unroll
            for (int mi = 0; mi < 4; mi++) {
#pragma unroll
                for (int np = 0; np < 2; np++) {
                    mma_f16(acc[mi][2 * np],     af[mi], &bf_cur[np][0]);
                    mma_f16(acc[mi][2 * np + 1], af[mi], &bf_cur[np][2]);
                }
            }
            if (kk < 3) {
#pragma unroll
                for (int np = 0; np < 2; np++)
#pragma unroll
                    for (int q = 0; q < 4; q++) bf_cur[np][q] = bf_nxt[np][q];
            }
        }
    }

    // ---- store logits ----
    float* Cb = C + (size_t)(bm + wm * 64) * VOC + bn + wn * 32;
#pragma unroll
    for (int mi = 0; mi < 4; mi++) {
#pragma unroll
        for (int ni = 0; ni < 4; ni++) {
            int r = mi * 16 + gid;
            int c = ni * 8 + tig * 2;
            float2 v0 = make_float2(acc[mi][ni][0], acc[mi][ni][1]);
            float2 v1 = make_float2(acc[mi][ni][2], acc[mi][ni][3]);
            *reinterpret_cast<float2*>(Cb + (size_t)r * VOC + c) = v0;
            *reinterpret_cast<float2*>(Cb + (size_t)(r + 8) * VOC + c) = v1;
        }
    }

    // ---- fused per-row softmax partials over this 128-col tile ----
    __syncthreads();
    float* pm = (float*)dyn_smem;
    float* ps = pm + 128 * 4;
#pragma unroll
    for (int mi = 0; mi < 4; mi++) {
#pragma unroll
        for (int h = 0; h < 2; h++) {
            float m0 = -1e30f;
#pragma unroll
            for (int ni = 0; ni < 4; ni++)
                m0 = fmaxf(m0, fmaxf(acc[mi][ni][2 * h], acc[mi][ni][2 * h + 1]));
            float s0 = 0.f;
#pragma unroll
            for (int ni = 0; ni < 4; ni++)
                s0 += __expf(acc[mi][ni][2 * h] - m0) + __expf(acc[mi][ni][2 * h + 1] - m0);
#pragma unroll
            for (int o = 1; o <= 2; o <<= 1) {
                float om = __shfl_xor_sync(0xffffffffu, m0, o);
                float os = __shfl_xor_sync(0xffffffffu, s0, o);
                float nm = fmaxf(m0, om);
                s0 = s0 * __expf(m0 - nm) + os * __expf(om - nm);
                m0 = nm;
            }
            if (tig == 0) {
                int lr = wm * 64 + mi * 16 + h * 8 + gid;
                pm[lr * 4 + wn] = m0;
                ps[lr * 4 + wn] = s0;
            }
        }
    }
    __syncthreads();
    if (tid < 128) {
        float m0 = pm[tid * 4], s0 = ps[tid * 4];
#pragma unroll
        for (int w = 1; w < 4; w++) {
            float om = pm[tid * 4 + w], os = ps[tid * 4 + w];
            float nm = fmaxf(m0, om);
            s0 = s0 * __expf(m0 - nm) + os * __expf(om - nm);
            m0 = nm;
        }
        // [s][nt] layout: coalesced reads in loss_reduce
        size_t idx = (size_t)(bm + tid) * NT + blockIdx.y;
        pmax[idx] = m0;
        psum[idx] = s0;
    }
}

// ---------------- loss: merge per-tile partials (coalesced) ----------------
__global__ void __launch_bounds__(256) loss_reduce_kernel(
    const float* __restrict__ logits, const float* __restrict__ pmax,
    const float* __restrict__ psum, const void* __restrict__ labels,
    const float* __restrict__ mask, float* __restrict__ nll_out)
{
    int s = blockIdx.x;
    int tid = threadIdx.x;
    const float* pmr = pmax + (size_t)s * NT;
    const float* psr = psum + (size_t)s * NT;
    float m = -1e30f, su = 0.f;
    for (int nt = tid; nt < NT; nt += 256) {
        float om = pmr[nt];
        float os = psr[nt];
        float nm = fmaxf(m, om);
        su = su * __expf(m - nm) + os * __expf(om - nm);
        m = nm;
    }
#pragma unroll
    for (int o = 16; o > 0; o >>= 1) {
        float om = __shfl_xor_sync(0xffffffffu, m, o);
        float os = __shfl_xor_sync(0xffffffffu, su, o);
        float nm = fmaxf(m, om);
        su = su * __expf(m - nm) + os * __expf(om - nm);
        m = nm;
    }
    __shared__ float sm[8], ssu[8];
    if ((tid & 31) == 0) { sm[tid >> 5] = m; ssu[tid >> 5] = su; }
    __syncthreads();
    if (tid == 0) {
        float M0 = sm[0], S0 = ssu[0];
#pragma unroll
        for (int i = 1; i < 8; i++) {
            float nm = fmaxf(M0, sm[i]);
            S0 = S0 * __expf(M0 - nm) + ssu[i] * __expf(sm[i] - nm);
            M0 = nm;
        }
        bool is64 = detect_i64((const int*)labels);
        int lab = load_idx(labels, s + 1, is64);
        float lse = M0 + logf(S0);
        float nll = lse - logits[(size_t)s * VOC + lab];
        nll_out[s] = nll * mask[s + 1];
    }
}

__global__ void __launch_bounds__(256) final_kernel(
    const float* __restrict__ nll, const float* __restrict__ mask,
    float* __restrict__ out)
{
    __shared__ float red[8];
    int tid = threadIdx.x;
    float a = 0.f, b = 0.f;
    for (int j = tid; j < SEQ - 1; j += 256) { a += nll[j]; b += mask[j + 1]; }
    a = block_sum256(a, red);
    b = block_sum256(b, red);
    if (tid == 0) out[0] = a / (b + 1e-8f);
}

// ---------------- launch ----------------
extern "C" void kernel_launch(void* const* d_in, const int* in_sizes, int n_in,
                              void* d_out, int out_size)
{
    const float* hidden  = (const float*)d_in[0];
    const void*  ids     = d_in[1];
    const void*  labels  = d_in[2];
    const float* maskp   = (const float*)d_in[3];
    const float* embed_w = (const float*)d_in[4];
    const float* enorm   = (const float*)d_in[5];
    const float* hnorm   = (const float*)d_in[6];
    const float* ehw     = (const float*)d_in[7];
    const float* lnw     = (const float*)d_in[8];
    const float* nw      = (const float*)d_in[9];
    const float* lmw     = (const float*)d_in[10];
    float* logits = (float*)d_out;

    void *pch, *pcl, *pwh, *pwl, *pp, *pa16, *pb16, *ppm, *pps, *pl;
    cudaGetSymbolAddress(&pch,  g_ch);
    cudaGetSymbolAddress(&pcl,  g_cl);
    cudaGetSymbolAddress(&pwh,  g_ewh);
    cudaGetSymbolAddress(&pwl,  g_ewl);
    cudaGetSymbolAddress(&pp,   g_proj);
    cudaGetSymbolAddress(&pa16, g_a16);
    cudaGetSymbolAddress(&pb16, g_b16);
    cudaGetSymbolAddress(&ppm,  g_pmax);
    cudaGetSymbolAddress(&pps,  g_psum);
    cudaGetSymbolAddress(&pl,   g_nll);

    cudaFuncSetAttribute(eh_fp16_kernel,
                         cudaFuncAttributeMaxDynamicSharedMemorySize, EH_SMEM);
    cudaFuncSetAttribute(lm_fp16_kernel,
                         cudaFuncAttributeMaxDynamicSharedMemorySize, LM_SMEM);

    // side streams + events (created lazily on the uncaptured correctness call)
    static cudaStream_t s2 = nullptr, s3 = nullptr;
    static cudaEvent_t evF = nullptr, evJ = nullptr, evP = nullptr;
    if (s2 == nullptr) {
        cudaStreamCreateWithFlags(&s2, cudaStreamNonBlocking);
        cudaStreamCreateWithFlags(&s3, cudaStreamNonBlocking);
        cudaEventCreateWithFlags(&evF, cudaEventDisableTiming);
        cudaEventCreateWithFlags(&evJ, cudaEventDisableTiming);
        cudaEventCreateWithFlags(&evP, cudaEventDisableTiming);
    }

    // fork
    cudaEventRecord(evF, 0);
    cudaStreamWaitEvent(s2, evF, 0);
    cudaStreamWaitEvent(s3, evF, 0);
    // s2: lm weight convert (long, overlaps entire eh chain)
    cvt_kernel<<<(int)(((size_t)VOC * HID) / (256 * 8)), 256, 0, s2>>>(lmw, (__half*)pb16);
    cudaEventRecord(evJ, s2);
    // s3: prep (independent of cvt_split)
    prep_kernel<<<SEQ, 256, 0, s3>>>(hidden, ids, embed_w, enorm, hnorm,
                                     (__half*)pch, (__half*)pcl);
    cudaEventRecord(evP, s3);

    // main chain
    cvt_split_kernel<<<(int)(((size_t)HID * K2DIM) / (256 * 8)), 256>>>(
        ehw, (__half*)pwh, (__half*)pwl);
    cudaStreamWaitEvent(0, evP, 0);
    eh_fp16_kernel<<<dim3(SEQ / 64, HID / 128), 256, EH_SMEM>>>(
        (const __half*)pch, (const __half*)pcl,
        (const __half*)pwh, (const __half*)pwl, (float*)pp);
    norm2_kernel<<<SEQ, 256>>>((const float*)pp, lnw, nw, (__half*)pa16);

    // join: lm_head needs both g_a16 and g_b16
    cudaStreamWaitEvent(0, evJ, 0);
    lm_fp16_kernel<<<dim3(SEQ / LM_BM, NT), 256, LM_SMEM>>>(
        (const __half*)pa16, (const __half*)pb16, logits, (float*)ppm, (float*)pps);
    loss_reduce_kernel<<<SEQ - 1, 256>>>(logits, (const float*)ppm, (const float*)pps,
                                         labels, maskp, (float*)pl);
    final_kernel<<<1, 256>>>((const float*)pl, maskp, logits + (size_t)SEQ * VOC);
}

// round 14
// speedup vs baseline: 1.0575x; 1.0575x over previous
#include <cuda.h>
#include <cuda_runtime.h>
#include <cuda_fp16.h>
#include <cstdint>

#define SEQ   1024
#define HID   2048
#define K2DIM 4096
#define VOC   129280
#define EPSV  1e-6f
#define NT    (VOC / 128)          // 1010 N-tiles (128-wide)

// single dynamic-smem symbol shared by all kernels
extern __shared__ char dyn_smem[];

// ---------------- scratch (device globals, no allocation) ----------------
__device__ __half g_ch[SEQ * K2DIM];                // 8 MB combined hi
__device__ __half g_cl[SEQ * K2DIM];                // 8 MB combined lo
__device__ __half g_ewh[(size_t)HID * K2DIM];       // 16 MB ehw hi
__device__ __half g_ewl[(size_t)HID * K2DIM];       // 16 MB ehw lo
__device__ float  g_proj[SEQ * HID];                // 8 MB
__device__ __half g_a16[SEQ * HID];                 // 4 MB (normed, fp16)
__device__ __half g_b16[(size_t)VOC * HID];         // 529 MB (lm_head_w fp16)
__device__ float  g_pmax[(size_t)SEQ * NT];         // [s][nt] coalesced for reduce
__device__ float  g_psum[(size_t)SEQ * NT];
__device__ float  g_nll[SEQ];

// ---------------- helpers ----------------
__device__ __forceinline__ unsigned h2_as_u32(__half2 h) {
    union { __half2 h; unsigned u; } c; c.h = h; return c.u;
}
__device__ __forceinline__ bool detect_i64(const int* w) {
    bool z = true;
#pragma unroll
    for (int j = 1; j < 32; j += 2) z = z && (w[j] == 0);
    return z;
}
__device__ __forceinline__ int load_idx(const void* p, int i, bool is64) {
    return is64 ? (int)((const long long*)p)[i] : ((const int*)p)[i];
}
__device__ __forceinline__ float block_sum256(float v, volatile float* red) {
#pragma unroll
    for (int o = 16; o > 0; o >>= 1) v += __shfl_xor_sync(0xffffffffu, v, o);
    if ((threadIdx.x & 31) == 0) red[threadIdx.x >> 5] = v;
    __syncthreads();
    float t = red[0] + red[1] + red[2] + red[3] + red[4] + red[5] + red[6] + red[7];
    __syncthreads();
    return t;
}

// .cg: bypass L1 (streamed GEMM operands have zero L1 reuse)
__device__ __forceinline__ void cp_async16(void* smem, const void* gmem) {
    unsigned sa = (unsigned)__cvta_generic_to_shared(smem);
    asm volatile("cp.async.cg.shared.global [%0], [%1], 16;" :: "r"(sa), "l"(gmem));
}
__device__ __forceinline__ void cp_commit() { asm volatile("cp.async.commit_group;"); }
__device__ __forceinline__ void cp_wait0() { asm volatile("cp.async.wait_group 0;"); }
__device__ __forceinline__ void cp_wait1() { asm volatile("cp.async.wait_group 1;"); }

__device__ __forceinline__ void ldsm_x4(uint32_t& r0, uint32_t& r1, uint32_t& r2,
                                        uint32_t& r3, uint32_t saddr) {
    asm volatile("ldmatrix.sync.aligned.m8n8.x4.shared.b16 {%0,%1,%2,%3}, [%4];"
        : "=r"(r0), "=r"(r1), "=r"(r2), "=r"(r3) : "r"(saddr));
}

__device__ __forceinline__ void mma_f16(float c[4], const uint32_t a[4], const uint32_t b[2]) {
    asm volatile(
        "mma.sync.aligned.m16n8k16.row.col.f32.f16.f16.f32 "
        "{%0,%1,%2,%3}, {%4,%5,%6,%7}, {%8,%9}, {%0,%1,%2,%3};"
        : "+f"(c[0]), "+f"(c[1]), "+f"(c[2]), "+f"(c[3])
        : "r"(a[0]), "r"(a[1]), "r"(a[2]), "r"(a[3]), "r"(b[0]), "r"(b[1]));
}

// ---------------- kernel A: gather + enorm + hnorm + concat (hi/lo fp16) ----
__global__ void __launch_bounds__(256) prep_kernel(
    const float* __restrict__ hidden, const void* __restrict__ ids,
    const float* __restrict__ embed_w, const float* __restrict__ enorm_w,
    const float* __restrict__ hnorm_w,
    __half* __restrict__ chi, __half* __restrict__ clo)
{
    __shared__ float s_e[HID];
    __shared__ float s_h[HID];
    __shared__ float red[8];
    __shared__ int s_id;
    int tid = threadIdx.x, sid = blockIdx.x;
    if (tid == 0) {
        bool is64 = detect_i64((const int*)ids);
        s_id = load_idx(ids, sid, is64);
    }
    __syncthreads();
    const float* erow = embed_w + (size_t)s_id * HID;
    const float* hrow = hidden + (size_t)sid * HID;
    float se = 0.f, sh = 0.f;
    for (int j = tid; j < HID; j += 256) {
        float e = erow[j], h = hrow[j];
        s_e[j] = e; s_h[j] = h;
        se += e * e; sh += h * h;
    }
    float vse = block_sum256(se, red);
    float vsh = block_sum256(sh, red);
    float re = rsqrtf(vse / HID + EPSV);
    float rh = rsqrtf(vsh / HID + EPSV);
    __half* oh = chi + (size_t)sid * K2DIM;
    __half* ol = clo + (size_t)sid * K2DIM;
    for (int j = tid; j < HID; j += 256) {
        float v0 = enorm_w[j] * s_e[j] * re;
        float v1 = hnorm_w[j] * s_h[j] * rh;
        __half h0 = __float2half_rn(v0);
        __half h1 = __float2half_rn(v1);
        oh[j]       = h0; ol[j]       = __float2half_rn(v0 - __half2float(h0));
        oh[HID + j] = h1; ol[HID + j] = __float2half_rn(v1 - __half2float(h1));
    }
}

// ---------------- double RMSNorm (ln then norm) -> fp16 output ----------------
__global__ void __launch_bounds__(256) norm2_kernel(
    const float* __restrict__ x, const float* __restrict__ lnw,
    const float* __restrict__ nw, __half* __restrict__ out)
{
    __shared__ float sx[HID];
    __shared__ float red[8];
    int sid = blockIdx.x, tid = threadIdx.x;
    const float* row = x + (size_t)sid * HID;
    float ss = 0.f;
    for (int j = tid; j < HID; j += 256) { float v = row[j]; sx[j] = v; ss += v * v; }
    float r1 = rsqrtf(block_sum256(ss, red) / HID + EPSV);
    float ss2 = 0.f;
    for (int j = tid; j < HID; j += 256) { float p = lnw[j] * sx[j] * r1; sx[j] = p; ss2 += p * p; }
    float r2 = rsqrtf(block_sum256(ss2, red) / HID + EPSV);
    __half* o = out + (size_t)sid * HID;
    for (int j = tid; j < HID; j += 256) o[j] = __float2half_rn(nw[j] * sx[j] * r2);
}

// ---------------- f32 -> f16 bulk convert (lm_head weights) ----------------
__global__ void __launch_bounds__(256) cvt_kernel(
    const float* __restrict__ in, __half* __restrict__ out)
{
    size_t i = ((size_t)blockIdx.x * 256 + threadIdx.x) * 8;
    float4 v0 = *reinterpret_cast<const float4*>(in + i);
    float4 v1 = *reinterpret_cast<const float4*>(in + i + 4);
    uint4 pk;
    pk.x = h2_as_u32(__floats2half2_rn(v0.x, v0.y));
    pk.y = h2_as_u32(__floats2half2_rn(v0.z, v0.w));
    pk.z = h2_as_u32(__floats2half2_rn(v1.x, v1.y));
    pk.w = h2_as_u32(__floats2half2_rn(v1.z, v1.w));
    *reinterpret_cast<uint4*>(out + i) = pk;
}

// ---------------- f32 -> (hi, lo) fp16 split convert (ehw) ----------------
__global__ void __launch_bounds__(256) cvt_split_kernel(
    const float* __restrict__ in, __half* __restrict__ hi, __half* __restrict__ lo)
{
    size_t i = ((size_t)blockIdx.x * 256 + threadIdx.x) * 8;
    float v[8];
    *reinterpret_cast<float4*>(v)     = *reinterpret_cast<const float4*>(in + i);
    *reinterpret_cast<float4*>(v + 4) = *reinterpret_cast<const float4*>(in + i + 4);
    __half h[8], l[8];
#pragma unroll
    for (int j = 0; j < 8; j++) {
        h[j] = __float2half_rn(v[j]);
        l[j] = __float2half_rn(v[j] - __half2float(h[j]));
    }
    *reinterpret_cast<uint4*>(hi + i) = *reinterpret_cast<uint4*>(h);
    *reinterpret_cast<uint4*>(lo + i) = *reinterpret_cast<uint4*>(l);
}

// =======================================================================
// eh_proj: 3-term split-fp16 GEMM (at tensor floor; R12 config)
// =======================================================================
#define EH_LDK  72
#define EH_A1   (64 * EH_LDK)
#define EH_B1   (128 * EH_LDK)
#define EH_STG  (2 * EH_A1 + 2 * EH_B1)
#define EH_SMEM (2 * EH_STG * 2)          // 110592 B -> 2 CTAs/SM
#define EH_KT   (K2DIM / 64)              // 64

__device__ __forceinline__ void eh_load_stage(
    const __half* __restrict__ Ah, const __half* __restrict__ Al,
    const __half* __restrict__ Bh, const __half* __restrict__ Bl,
    __half* smem, int kt, int s, int bm, int bn, int tid)
{
    __half* st = smem + s * EH_STG;
    size_t a0 = (size_t)bm * K2DIM + kt * 64;
    size_t b0 = (size_t)bn * K2DIM + kt * 64;
#pragma unroll
    for (int i = 0; i < 2; i++) {
        int c = tid + i * 256;
        int r = c >> 3, kc = (c & 7) * 8;
        int so = r * EH_LDK + kc;
        cp_async16(st + so,          Ah + a0 + (size_t)r * K2DIM + kc);
        cp_async16(st + EH_A1 + so,  Al + a0 + (size_t)r * K2DIM + kc);
    }
#pragma unroll
    for (int i = 0; i < 4; i++) {
        int c = tid + i * 256;
        int r = c >> 3, kc = (c & 7) * 8;
        int so = r * EH_LDK + kc;
        cp_async16(st + 2 * EH_A1 + so,          Bh + b0 + (size_t)r * K2DIM + kc);
        cp_async16(st + 2 * EH_A1 + EH_B1 + so,  Bl + b0 + (size_t)r * K2DIM + kc);
    }
}

__global__ void __launch_bounds__(256, 2) eh_fp16_kernel(
    const __half* __restrict__ Ah, const __half* __restrict__ Al,
    const __half* __restrict__ Bh, const __half* __restrict__ Bl,
    float* __restrict__ C)
{
    __half* smem = (__half*)dyn_smem;
    int tid = threadIdx.x;
    int lane = tid & 31, warp = tid >> 5;
    int wm = warp & 1, wn = warp >> 1;
    int gid = lane >> 2, tig = lane & 3;
    int bm = blockIdx.x * 64;
    int bn = blockIdx.y * 128;

    float acc[2][4][4];
#pragma unroll
    for (int i = 0; i < 2; i++)
#pragma unroll
        for (int j = 0; j < 4; j++)
#pragma unroll
            for (int q = 0; q < 4; q++) acc[i][j][q] = 0.f;

    uint32_t smem_u = (uint32_t)__cvta_generic_to_shared(smem);
    int a_off = (wm * 32 + (lane & 15)) * EH_LDK + ((lane >> 4) << 3);
    int b_off = (wn * 32 + ((lane >> 4) << 3) + (lane & 7)) * EH_LDK + (((lane >> 3) & 1) << 3);

    eh_load_stage(Ah, Al, Bh, Bl, smem, 0, 0, bm, bn, tid); cp_commit();

    for (int kt = 0; kt < EH_KT; ++kt) {
        if (kt + 1 < EH_KT) {
            eh_load_stage(Ah, Al, Bh, Bl, smem, kt + 1, (kt + 1) & 1, bm, bn, tid);
            cp_commit();
            cp_wait1();
        } else {
            cp_wait0();
        }
        __syncthreads();
        uint32_t stg = (kt & 1) * EH_STG;
        uint32_t ah_base = smem_u + (stg + a_off) * 2;
        uint32_t al_base = ah_base + EH_A1 * 2;
        uint32_t bh_base = smem_u + (stg + 2 * EH_A1 + b_off) * 2;
        uint32_t bl_base = bh_base + EH_B1 * 2;
#pragma unroll
        for (int kk = 0; kk < 4; kk++) {
            uint32_t ahf[2][4], alf[2][4], bhf[2][4], blf[2][4];
#pragma unroll
            for (int mi = 0; mi < 2; mi++) {
                ldsm_x4(ahf[mi][0], ahf[mi][1], ahf[mi][2], ahf[mi][3],
                        ah_base + (mi * 16 * EH_LDK + kk * 16) * 2);
                ldsm_x4(alf[mi][0], alf[mi][1], alf[mi][2], alf[mi][3],
                        al_base + (mi * 16 * EH_LDK + kk * 16) * 2);
            }
#pragma unroll
            for (int np = 0; np < 2; np++) {
                ldsm_x4(bhf[np][0], bhf[np][1], bhf[np][2], bhf[np][3],
                        bh_base + (np * 16 * EH_LDK + kk * 16) * 2);
                ldsm_x4(blf[np][0], blf[np][1], blf[np][2], blf[np][3],
                        bl_base + (np * 16 * EH_LDK + kk * 16) * 2);
            }
#pragma unroll
            for (int mi = 0; mi < 2; mi++) {
#pragma unroll
                for (int np = 0; np < 2; np++) {
                    mma_f16(acc[mi][2 * np],     ahf[mi], &bhf[np][0]);
                    mma_f16(acc[mi][2 * np + 1], ahf[mi], &bhf[np][2]);
                    mma_f16(acc[mi][2 * np],     ahf[mi], &blf[np][0]);
                    mma_f16(acc[mi][2 * np + 1], ahf[mi], &blf[np][2]);
                    mma_f16(acc[mi][2 * np],     alf[mi], &bhf[np][0]);
                    mma_f16(acc[mi][2 * np + 1], alf[mi], &bhf[np][2]);
                }
            }
        }
        __syncthreads();
    }

    float* Cb = C + (size_t)(bm + wm * 32) * HID + bn + wn * 32;
#pragma unroll
    for (int mi = 0; mi < 2; mi++) {
#pragma unroll
        for (int ni = 0; ni < 4; ni++) {
            int r = mi * 16 + gid;
            int c = ni * 8 + tig * 2;
            float2 v0 = make_float2(acc[mi][ni][0], acc[mi][ni][1]);
            float2 v1 = make_float2(acc[mi][ni][2], acc[mi][ni][3]);
            *reinterpret_cast<float2*>(Cb + (size_t)r * HID + c) = v0;
            *reinterpret_cast<float2*>(Cb + (size_t)(r + 8) * HID + c) = v1;
        }
    }
}

// =======================================================================
// lm_head: fp16 mma.sync GEMM + fused softmax partials
//   R9/R11 mainloop (best measured), [s][nt] coalesced partials, .cg loads.
// =======================================================================
#define LM_BM   128
#define LM_BN   128
#define LM_BK   64
#define LM_LDK  72
#define LM_ASZ  (LM_BM * LM_LDK)
#define LM_BSZ  (LM_BN * LM_LDK)
#define LM_STG  (LM_ASZ + LM_BSZ)
#define LM_SMEM (3 * LM_STG * 2)         // 110592 B
#define LM_KT   (HID / LM_BK)            // 32

__device__ __forceinline__ void lm_load_stage(
    const __half* __restrict__ A16, const __half* __restrict__ B16,
    __half* smem, int kt, int s, int bm, int bn, int tid)
{
    __half* as = smem + s * LM_STG;
    __half* bs = as + LM_ASZ;
    const __half* Ag = A16 + (size_t)bm * HID + kt * LM_BK;
    const __half* Bg = B16 + (size_t)bn * HID + kt * LM_BK;
#pragma unroll
    for (int i = 0; i < 4; i++) {
        int c = tid + i * 256;
        int r = c >> 3, kc = (c & 7) * 8;
        cp_async16(as + r * LM_LDK + kc, Ag + (size_t)r * HID + kc);
    }
#pragma unroll
    for (int i = 0; i < 4; i++) {
        int c = tid + i * 256;
        int r = c >> 3, kc = (c & 7) * 8;
        cp_async16(bs + r * LM_LDK + kc, Bg + (size_t)r * HID + kc);
    }
}

__global__ void __launch_bounds__(256, 2) lm_fp16_kernel(
    const __half* __restrict__ A16, const __half* __restrict__ B16,
    float* __restrict__ C, float* __restrict__ pmax, float* __restrict__ psum)
{
    __half* smem = (__half*)dyn_smem;
    int tid = threadIdx.x;
    int lane = tid & 31, warp = tid >> 5;
    int wm = warp & 1, wn = warp >> 1;
    int gid = lane >> 2, tig = lane & 3;
    int bm = blockIdx.x * LM_BM;
    int bn = blockIdx.y * LM_BN;

    float acc[4][4][4];
#pragma unroll
    for (int i = 0; i < 4; i++)
#pragma unroll
        for (int j = 0; j < 4; j++)
#pragma unroll
            for (int q = 0; q < 4; q++) acc[i][j][q] = 0.f;

    uint32_t smem_u = (uint32_t)__cvta_generic_to_shared(smem);
    int a_off = (wm * 64 + (lane & 15)) * LM_LDK + ((lane >> 4) << 3);
    int b_off = (wn * 32 + ((lane >> 4) << 3) + (lane & 7)) * LM_LDK + (((lane >> 3) & 1) << 3);

    lm_load_stage(A16, B16, smem, 0, 0, bm, bn, tid); cp_commit();
    lm_load_stage(A16, B16, smem, 1, 1, bm, bn, tid); cp_commit();

    for (int kt = 0; kt < LM_KT; ++kt) {
        if (kt >= LM_KT - 2) cp_wait0(); else cp_wait1();
        __syncthreads();
        if (kt + 2 < LM_KT) {
            lm_load_stage(A16, B16, smem, kt + 2, (kt + 2) % 3, bm, bn, tid);
            cp_commit();
        }
        uint32_t a_base = smem_u + ((kt % 3) * LM_STG + a_off) * 2;
        uint32_t b_base = smem_u + ((kt % 3) * LM_STG + LM_ASZ + b_off) * 2;
#pragma unroll
        for (int kk = 0; kk < 4; kk++) {
            uint32_t af[4][4], bf4[2][4];
#pragma unroll
            for (int mi = 0; mi < 4; mi++)
                ldsm_x4(af[mi][0], af[mi][1], af[mi][2], af[mi][3],
                        a_base + (mi * 16 * LM_LDK + kk * 16) * 2);
#pragma unroll
            for (int np = 0; np < 2; np++)
                ldsm_x4(bf4[np][0], bf4[np][1], bf4[np][2], bf4[np][3],
                        b_base + (np * 16 * LM_LDK + kk * 16) * 2);
#pragma unroll
            for (int mi = 0; mi < 4; mi++) {
#pragma unroll
                for (int np = 0; np < 2; np++) {
                    mma_f16(acc[mi][2 * np],     af[mi], &bf4[np][0]);
                    mma_f16(acc[mi][2 * np + 1], af[mi], &bf4[np][2]);
                }
            }
        }
    }

    // ---- store logits ----
    float* Cb = C + (size_t)(bm + wm * 64) * VOC + bn + wn * 32;
#pragma unroll
    for (int mi = 0; mi < 4; mi++) {
#pragma unroll
        for (int ni = 0; ni < 4; ni++) {
            int r = mi * 16 + gid;
            int c = ni * 8 + tig * 2;
            float2 v0 = make_float2(acc[mi][ni][0], acc[mi][ni][1]);
            float2 v1 = make_float2(acc[mi][ni][2], acc[mi][ni][3]);
            *reinterpret_cast<float2*>(Cb + (size_t)r * VOC + c) = v0;
            *reinterpret_cast<float2*>(Cb + (size_t)(r + 8) * VOC + c) = v1;
        }
    }

    // ---- fused per-row softmax partials over this 128-col tile ----
    __syncthreads();
    float* pm = (float*)dyn_smem;
    float* ps = pm + 128 * 4;
#pragma unroll
    for (int mi = 0; mi < 4; mi++) {
#pragma unroll
        for (int h = 0; h < 2; h++) {
            float m0 = -1e30f;
#pragma unroll
            for (int ni = 0; ni < 4; ni++)
                m0 = fmaxf(m0, fmaxf(acc[mi][ni][2 * h], acc[mi][ni][2 * h + 1]));
            float s0 = 0.f;
#pragma unroll
            for (int ni = 0; ni < 4; ni++)
                s0 += __expf(acc[mi][ni][2 * h] - m0) + __expf(acc[mi][ni][2 * h + 1] - m0);
#pragma unroll
            for (int o = 1; o <= 2; o <<= 1) {
                float om = __shfl_xor_sync(0xffffffffu, m0, o);
                float os = __shfl_xor_sync(0xffffffffu, s0, o);
                float nm = fmaxf(m0, om);
                s0 = s0 * __expf(m0 - nm) + os * __expf(om - nm);
                m0 = nm;
            }
            if (tig == 0) {
                int lr = wm * 64 + mi * 16 + h * 8 + gid;
                pm[lr * 4 + wn] = m0;
                ps[lr * 4 + wn] = s0;
            }
        }
    }
    __syncthreads();
    if (tid < 128) {
        float m0 = pm[tid * 4], s0 = ps[tid * 4];
#pragma unroll
        for (int w = 1; w < 4; w++) {
            float om = pm[tid * 4 + w], os = ps[tid * 4 + w];
            float nm = fmaxf(m0, om);
            s0 = s0 * __expf(m0 - nm) + os * __expf(om - nm);
            m0 = nm;
        }
        // [s][nt] layout: coalesced reads in loss_reduce
        size_t idx = (size_t)(bm + tid) * NT + blockIdx.y;
        pmax[idx] = m0;
        psum[idx] = s0;
    }
}

// ---------------- loss: merge per-tile partials (coalesced) ----------------
__global__ void __launch_bounds__(256) loss_reduce_kernel(
    const float* __restrict__ logits, const float* __restrict__ pmax,
    const float* __restrict__ psum, const void* __restrict__ labels,
    const float* __restrict__ mask, float* __restrict__ nll_out)
{
    int s = blockIdx.x;
    int tid = threadIdx.x;
    const float* pmr = pmax + (size_t)s * NT;
    const float* psr = psum + (size_t)s * NT;
    float m = -1e30f, su = 0.f;
    for (int nt = tid; nt < NT; nt += 256) {
        float om = pmr[nt];
        float os = psr[nt];
        float nm = fmaxf(m, om);
        su = su * __expf(m - nm) + os * __expf(om - nm);
        m = nm;
    }
#pragma unroll
    for (int o = 16; o > 0; o >>= 1) {
        float om = __shfl_xor_sync(0xffffffffu, m, o);
        float os = __shfl_xor_sync(0xffffffffu, su, o);
        float nm = fmaxf(m, om);
        su = su * __expf(m - nm) + os * __expf(om - nm);
        m = nm;
    }
    __shared__ float sm[8], ssu[8];
    if ((tid & 31) == 0) { sm[tid >> 5] = m; ssu[tid >> 5] = su; }
    __syncthreads();
    if (tid == 0) {
        float M0 = sm[0], S0 = ssu[0];
#pragma unroll
        for (int i = 1; i < 8; i++) {
            float nm = fmaxf(M0, sm[i]);
            S0 = S0 * __expf(M0 - nm) + ssu[i] * __expf(sm[i] - nm);
            M0 = nm;
        }
        bool is64 = detect_i64((const int*)labels);
        int lab = load_idx(labels, s + 1, is64);
        float lse = M0 + logf(S0);
        float nll = lse - logits[(size_t)s * VOC + lab];
        nll_out[s] = nll * mask[s + 1];
    }
}

__global__ void __launch_bounds__(256) final_kernel(
    const float* __restrict__ nll, const float* __restrict__ mask,
    float* __restrict__ out)
{
    __shared__ float red[8];
    int tid = threadIdx.x;
    float a = 0.f, b = 0.f;
    for (int j = tid; j < SEQ - 1; j += 256) { a += nll[j]; b += mask[j + 1]; }
    a = block_sum256(a, red);
    b = block_sum256(b, red);
    if (tid == 0) out[0] = a / (b + 1e-8f);
}

// ---------------- launch ----------------
extern "C" void kernel_launch(void* const* d_in, const int* in_sizes, int n_in,
                              void* d_out, int out_size)
{
    const float* hidden  = (const float*)d_in[0];
    const void*  ids     = d_in[1];
    const void*  labels  = d_in[2];
    const float* maskp   = (const float*)d_in[3];
    const float* embed_w = (const float*)d_in[4];
    const float* enorm   = (const float*)d_in[5];
    const float* hnorm   = (const float*)d_in[6];
    const float* ehw     = (const float*)d_in[7];
    const float* lnw     = (const float*)d_in[8];
    const float* nw      = (const float*)d_in[9];
    const float* lmw     = (const float*)d_in[10];
    float* logits = (float*)d_out;

    void *pch, *pcl, *pwh, *pwl, *pp, *pa16, *pb16, *ppm, *pps, *pl;
    cudaGetSymbolAddress(&pch,  g_ch);
    cudaGetSymbolAddress(&pcl,  g_cl);
    cudaGetSymbolAddress(&pwh,  g_ewh);
    cudaGetSymbolAddress(&pwl,  g_ewl);
    cudaGetSymbolAddress(&pp,   g_proj);
    cudaGetSymbolAddress(&pa16, g_a16);
    cudaGetSymbolAddress(&pb16, g_b16);
    cudaGetSymbolAddress(&ppm,  g_pmax);
    cudaGetSymbolAddress(&pps,  g_psum);
    cudaGetSymbolAddress(&pl,   g_nll);

    cudaFuncSetAttribute(eh_fp16_kernel,
                         cudaFuncAttributeMaxDynamicSharedMemorySize, EH_SMEM);
    cudaFuncSetAttribute(lm_fp16_kernel,
                         cudaFuncAttributeMaxDynamicSharedMemorySize, LM_SMEM);

    // side streams + events (created lazily on the uncaptured correctness call)
    static cudaStream_t s2 = nullptr, s3 = nullptr;
    static cudaEvent_t evF = nullptr, evJ = nullptr, evP = nullptr;
    if (s2 == nullptr) {
        cudaStreamCreateWithFlags(&s2, cudaStreamNonBlocking);
        cudaStreamCreateWithFlags(&s3, cudaStreamNonBlocking);
        cudaEventCreateWithFlags(&evF, cudaEventDisableTiming);
        cudaEventCreateWithFlags(&evJ, cudaEventDisableTiming);
        cudaEventCreateWithFlags(&evP, cudaEventDisableTiming);
    }

    // fork
    cudaEventRecord(evF, 0);
    cudaStreamWaitEvent(s2, evF, 0);
    cudaStreamWaitEvent(s3, evF, 0);
    // s2: lm weight convert (long, overlaps entire eh chain)
    cvt_kernel<<<(int)(((size_t)VOC * HID) / (256 * 8)), 256, 0, s2>>>(lmw, (__half*)pb16);
    cudaEventRecord(evJ, s2);
    // s3: prep (independent of cvt_split)
    prep_kernel<<<SEQ, 256, 0, s3>>>(hidden, ids, embed_w, enorm, hnorm,
                                     (__half*)pch, (__half*)pcl);
    cudaEventRecord(evP, s3);

    // main chain
    cvt_split_kernel<<<(int)(((size_t)HID * K2DIM) / (256 * 8)), 256>>>(
        ehw, (__half*)pwh, (__half*)pwl);
    cudaStreamWaitEvent(0, evP, 0);
    eh_fp16_kernel<<<dim3(SEQ / 64, HID / 128), 256, EH_SMEM>>>(
        (const __half*)pch, (const __half*)pcl,
        (const __half*)pwh, (const __half*)pwl, (float*)pp);
    norm2_kernel<<<SEQ, 256>>>((const float*)pp, lnw, nw, (__half*)pa16);

    // join: lm_head needs both g_a16 and g_b16
    cudaStreamWaitEvent(0, evJ, 0);
    lm_fp16_kernel<<<dim3(SEQ / LM_BM, NT), 256, LM_SMEM>>>(
        (const __half*)pa16, (const __half*)pb16, logits, (float*)ppm, (float*)pps);
    loss_reduce_kernel<<<SEQ - 1, 256>>>(logits, (const float*)ppm, (const float*)pps,
                                         labels, maskp, (float*)pl);
    final_kernel<<<1, 256>>>((const float*)pl, maskp, logits + (size_t)SEQ * VOC);
}

// round 15
// speedup vs baseline: 1.0845x; 1.0255x over previous
#include <cuda.h>
#include <cuda_runtime.h>
#include <cuda_fp16.h>
#include <cstdint>

#define SEQ   1024
#define HID   2048
#define K2DIM 4096
#define VOC   129280
#define EPSV  1e-6f
#define NT    (VOC / 128)          // 1010 N-tiles (128-wide)

// single dynamic-smem symbol shared by all kernels
extern __shared__ char dyn_smem[];

// ---------------- scratch (device globals, no allocation) ----------------
__device__ __half g_ch[SEQ * K2DIM];                // 8 MB combined hi (fp16)
__device__ __half g_ewh[(size_t)HID * K2DIM];       // 16 MB ehw hi
__device__ __half g_ewl[(size_t)HID * K2DIM];       // 16 MB ehw lo
__device__ float  g_proj[SEQ * HID];                // 8 MB
__device__ __half g_a16[SEQ * HID];                 // 4 MB (normed, fp16)
__device__ __half g_b16[(size_t)VOC * HID];         // 529 MB (lm_head_w fp16)
__device__ float  g_pmax[(size_t)SEQ * NT];         // [s][nt] coalesced for reduce
__device__ float  g_psum[(size_t)SEQ * NT];
__device__ float  g_nll[SEQ];

// ---------------- helpers ----------------
__device__ __forceinline__ unsigned h2_as_u32(__half2 h) {
    union { __half2 h; unsigned u; } c; c.h = h; return c.u;
}
__device__ __forceinline__ bool detect_i64(const int* w) {
    bool z = true;
#pragma unroll
    for (int j = 1; j < 32; j += 2) z = z && (w[j] == 0);
    return z;
}
__device__ __forceinline__ int load_idx(const void* p, int i, bool is64) {
    return is64 ? (int)((const long long*)p)[i] : ((const int*)p)[i];
}
__device__ __forceinline__ float block_sum256(float v, volatile float* red) {
#pragma unroll
    for (int o = 16; o > 0; o >>= 1) v += __shfl_xor_sync(0xffffffffu, v, o);
    if ((threadIdx.x & 31) == 0) red[threadIdx.x >> 5] = v;
    __syncthreads();
    float t = red[0] + red[1] + red[2] + red[3] + red[4] + red[5] + red[6] + red[7];
    __syncthreads();
    return t;
}

// .cg: bypass L1 (streamed GEMM operands have zero L1 reuse)
__device__ __forceinline__ void cp_async16(void* smem, const void* gmem) {
    unsigned sa = (unsigned)__cvta_generic_to_shared(smem);
    asm volatile("cp.async.cg.shared.global [%0], [%1], 16;" :: "r"(sa), "l"(gmem));
}
__device__ __forceinline__ void cp_commit() { asm volatile("cp.async.commit_group;"); }
__device__ __forceinline__ void cp_wait0() { asm volatile("cp.async.wait_group 0;"); }
__device__ __forceinline__ void cp_wait1() { asm volatile("cp.async.wait_group 1;"); }

__device__ __forceinline__ void ldsm_x4(uint32_t& r0, uint32_t& r1, uint32_t& r2,
                                        uint32_t& r3, uint32_t saddr) {
    asm volatile("ldmatrix.sync.aligned.m8n8.x4.shared.b16 {%0,%1,%2,%3}, [%4];"
        : "=r"(r0), "=r"(r1), "=r"(r2), "=r"(r3) : "r"(saddr));
}

__device__ __forceinline__ void mma_f16(float c[4], const uint32_t a[4], const uint32_t b[2]) {
    asm volatile(
        "mma.sync.aligned.m16n8k16.row.col.f32.f16.f16.f32 "
        "{%0,%1,%2,%3}, {%4,%5,%6,%7}, {%8,%9}, {%0,%1,%2,%3};"
        : "+f"(c[0]), "+f"(c[1]), "+f"(c[2]), "+f"(c[3])
        : "r"(a[0]), "r"(a[1]), "r"(a[2]), "r"(a[3]), "r"(b[0]), "r"(b[1]));
}

// streaming store (evict-first): keep L2 for B-tile reuse
__device__ __forceinline__ void st_cs_f2(float* p, float2 v) {
    asm volatile("st.global.cs.v2.f32 [%0], {%1, %2};" :: "l"(p), "f"(v.x), "f"(v.y) : "memory");
}

// ---------------- kernel A: gather + enorm + hnorm + concat (fp16 hi) ----
__global__ void __launch_bounds__(256) prep_kernel(
    const float* __restrict__ hidden, const void* __restrict__ ids,
    const float* __restrict__ embed_w, const float* __restrict__ enorm_w,
    const float* __restrict__ hnorm_w, __half* __restrict__ chi)
{
    __shared__ float s_e[HID];
    __shared__ float s_h[HID];
    __shared__ float red[8];
    __shared__ int s_id;
    int tid = threadIdx.x, sid = blockIdx.x;
    if (tid == 0) {
        bool is64 = detect_i64((const int*)ids);
        s_id = load_idx(ids, sid, is64);
    }
    __syncthreads();
    const float* erow = embed_w + (size_t)s_id * HID;
    const float* hrow = hidden + (size_t)sid * HID;
    float se = 0.f, sh = 0.f;
    for (int j = tid; j < HID; j += 256) {
        float e = erow[j], h = hrow[j];
        s_e[j] = e; s_h[j] = h;
        se += e * e; sh += h * h;
    }
    float vse = block_sum256(se, red);
    float vsh = block_sum256(sh, red);
    float re = rsqrtf(vse / HID + EPSV);
    float rh = rsqrtf(vsh / HID + EPSV);
    __half* oh = chi + (size_t)sid * K2DIM;
    for (int j = tid; j < HID; j += 256) {
        oh[j]       = __float2half_rn(enorm_w[j] * s_e[j] * re);
        oh[HID + j] = __float2half_rn(hnorm_w[j] * s_h[j] * rh);
    }
}

// ---------------- double RMSNorm (ln then norm) -> fp16 output ----------------
__global__ void __launch_bounds__(256) norm2_kernel(
    const float* __restrict__ x, const float* __restrict__ lnw,
    const float* __restrict__ nw, __half* __restrict__ out)
{
    __shared__ float sx[HID];
    __shared__ float red[8];
    int sid = blockIdx.x, tid = threadIdx.x;
    const float* row = x + (size_t)sid * HID;
    float ss = 0.f;
    for (int j = tid; j < HID; j += 256) { float v = row[j]; sx[j] = v; ss += v * v; }
    float r1 = rsqrtf(block_sum256(ss, red) / HID + EPSV);
    float ss2 = 0.f;
    for (int j = tid; j < HID; j += 256) { float p = lnw[j] * sx[j] * r1; sx[j] = p; ss2 += p * p; }
    float r2 = rsqrtf(block_sum256(ss2, red) / HID + EPSV);
    __half* o = out + (size_t)sid * HID;
    for (int j = tid; j < HID; j += 256) o[j] = __float2half_rn(nw[j] * sx[j] * r2);
}

// ---------------- f32 -> f16 bulk convert (lm_head weights) ----------------
__global__ void __launch_bounds__(256) cvt_kernel(
    const float* __restrict__ in, __half* __restrict__ out)
{
    size_t i = ((size_t)blockIdx.x * 256 + threadIdx.x) * 8;
    float4 v0 = *reinterpret_cast<const float4*>(in + i);
    float4 v1 = *reinterpret_cast<const float4*>(in + i + 4);
    uint4 pk;
    pk.x = h2_as_u32(__floats2half2_rn(v0.x, v0.y));
    pk.y = h2_as_u32(__floats2half2_rn(v0.z, v0.w));
    pk.z = h2_as_u32(__floats2half2_rn(v1.x, v1.y));
    pk.w = h2_as_u32(__floats2half2_rn(v1.z, v1.w));
    *reinterpret_cast<uint4*>(out + i) = pk;
}

// ---------------- f32 -> (hi, lo) fp16 split convert (ehw) ----------------
__global__ void __launch_bounds__(256) cvt_split_kernel(
    const float* __restrict__ in, __half* __restrict__ hi, __half* __restrict__ lo)
{
    size_t i = ((size_t)blockIdx.x * 256 + threadIdx.x) * 8;
    float v[8];
    *reinterpret_cast<float4*>(v)     = *reinterpret_cast<const float4*>(in + i);
    *reinterpret_cast<float4*>(v + 4) = *reinterpret_cast<const float4*>(in + i + 4);
    __half h[8], l[8];
#pragma unroll
    for (int j = 0; j < 8; j++) {
        h[j] = __float2half_rn(v[j]);
        l[j] = __float2half_rn(v[j] - __half2float(h[j]));
    }
    *reinterpret_cast<uint4*>(hi + i) = *reinterpret_cast<uint4*>(h);
    *reinterpret_cast<uint4*>(lo + i) = *reinterpret_cast<uint4*>(l);
}

// =======================================================================
// eh_proj: 2-term split-fp16 GEMM  proj = Ah*(Bh + Bl)
//   CTA 64x128, 8 warps (2M x 4N, 32x32), BK=64, 2-stage, 2 CTAs/SM.
// =======================================================================
#define EH_LDK  72
#define EH_A1   (64 * EH_LDK)             // 4608 halves (Ah)
#define EH_B1   (128 * EH_LDK)            // 9216 halves (one B matrix)
#define EH_STG  (EH_A1 + 2 * EH_B1)       // 23040 halves = 46080 B
#define EH_SMEM (2 * EH_STG * 2)          // 92160 B -> 2 CTAs/SM
#define EH_KT   (K2DIM / 64)              // 64

__device__ __forceinline__ void eh_load_stage(
    const __half* __restrict__ Ah,
    const __half* __restrict__ Bh, const __half* __restrict__ Bl,
    __half* smem, int kt, int s, int bm, int bn, int tid)
{
    __half* st = smem + s * EH_STG;
    size_t a0 = (size_t)bm * K2DIM + kt * 64;
    size_t b0 = (size_t)bn * K2DIM + kt * 64;
#pragma unroll
    for (int i = 0; i < 2; i++) {          // Ah: 512 chunks
        int c = tid + i * 256;
        int r = c >> 3, kc = (c & 7) * 8;
        cp_async16(st + r * EH_LDK + kc, Ah + a0 + (size_t)r * K2DIM + kc);
    }
#pragma unroll
    for (int i = 0; i < 4; i++) {          // Bh, Bl: 1024 chunks each
        int c = tid + i * 256;
        int r = c >> 3, kc = (c & 7) * 8;
        int so = r * EH_LDK + kc;
        cp_async16(st + EH_A1 + so,          Bh + b0 + (size_t)r * K2DIM + kc);
        cp_async16(st + EH_A1 + EH_B1 + so,  Bl + b0 + (size_t)r * K2DIM + kc);
    }
}

__global__ void __launch_bounds__(256, 2) eh_fp16_kernel(
    const __half* __restrict__ Ah,
    const __half* __restrict__ Bh, const __half* __restrict__ Bl,
    float* __restrict__ C)
{
    __half* smem = (__half*)dyn_smem;
    int tid = threadIdx.x;
    int lane = tid & 31, warp = tid >> 5;
    int wm = warp & 1, wn = warp >> 1;
    int gid = lane >> 2, tig = lane & 3;
    int bm = blockIdx.x * 64;
    int bn = blockIdx.y * 128;

    float acc[2][4][4];
#pragma unroll
    for (int i = 0; i < 2; i++)
#pragma unroll
        for (int j = 0; j < 4; j++)
#pragma unroll
            for (int q = 0; q < 4; q++) acc[i][j][q] = 0.f;

    uint32_t smem_u = (uint32_t)__cvta_generic_to_shared(smem);
    int a_off = (wm * 32 + (lane & 15)) * EH_LDK + ((lane >> 4) << 3);
    int b_off = (wn * 32 + ((lane >> 4) << 3) + (lane & 7)) * EH_LDK + (((lane >> 3) & 1) << 3);

    eh_load_stage(Ah, Bh, Bl, smem, 0, 0, bm, bn, tid); cp_commit();

    for (int kt = 0; kt < EH_KT; ++kt) {
        if (kt + 1 < EH_KT) {
            eh_load_stage(Ah, Bh, Bl, smem, kt + 1, (kt + 1) & 1, bm, bn, tid);
            cp_commit();
            cp_wait1();
        } else {
            cp_wait0();
        }
        __syncthreads();
        uint32_t stg = (kt & 1) * EH_STG;
        uint32_t ah_base = smem_u + (stg + a_off) * 2;
        uint32_t bh_base = smem_u + (stg + EH_A1 + b_off) * 2;
        uint32_t bl_base = bh_base + EH_B1 * 2;
#pragma unroll
        for (int kk = 0; kk < 4; kk++) {
            uint32_t ahf[2][4], bhf[2][4], blf[2][4];
#pragma unroll
            for (int mi = 0; mi < 2; mi++)
                ldsm_x4(ahf[mi][0], ahf[mi][1], ahf[mi][2], ahf[mi][3],
                        ah_base + (mi * 16 * EH_LDK + kk * 16) * 2);
#pragma unroll
            for (int np = 0; np < 2; np++) {
                ldsm_x4(bhf[np][0], bhf[np][1], bhf[np][2], bhf[np][3],
                        bh_base + (np * 16 * EH_LDK + kk * 16) * 2);
                ldsm_x4(blf[np][0], blf[np][1], blf[np][2], blf[np][3],
                        bl_base + (np * 16 * EH_LDK + kk * 16) * 2);
            }
#pragma unroll
            for (int mi = 0; mi < 2; mi++) {
#pragma unroll
                for (int np = 0; np < 2; np++) {
                    mma_f16(acc[mi][2 * np],     ahf[mi], &bhf[np][0]);
                    mma_f16(acc[mi][2 * np + 1], ahf[mi], &bhf[np][2]);
                    mma_f16(acc[mi][2 * np],     ahf[mi], &blf[np][0]);
                    mma_f16(acc[mi][2 * np + 1], ahf[mi], &blf[np][2]);
                }
            }
        }
        __syncthreads();
    }

    float* Cb = C + (size_t)(bm + wm * 32) * HID + bn + wn * 32;
#pragma unroll
    for (int mi = 0; mi < 2; mi++) {
#pragma unroll
        for (int ni = 0; ni < 4; ni++) {
            int r = mi * 16 + gid;
            int c = ni * 8 + tig * 2;
            float2 v0 = make_float2(acc[mi][ni][0], acc[mi][ni][1]);
            float2 v1 = make_float2(acc[mi][ni][2], acc[mi][ni][3]);
            *reinterpret_cast<float2*>(Cb + (size_t)r * HID + c) = v0;
            *reinterpret_cast<float2*>(Cb + (size_t)(r + 8) * HID + c) = v1;
        }
    }
}

// =======================================================================
// lm_head: fp16 mma.sync GEMM + fused softmax partials
//   R9/R11 mainloop, .cg loads, streaming logits stores, [s][nt] partials.
// =======================================================================
#define LM_BM   128
#define LM_BN   128
#define LM_BK   64
#define LM_LDK  72
#define LM_ASZ  (LM_BM * LM_LDK)
#define LM_BSZ  (LM_BN * LM_LDK)
#define LM_STG  (LM_ASZ + LM_BSZ)
#define LM_SMEM (3 * LM_STG * 2)         // 110592 B
#define LM_KT   (HID / LM_BK)            // 32

__device__ __forceinline__ void lm_load_stage(
    const __half* __restrict__ A16, const __half* __restrict__ B16,
    __half* smem, int kt, int s, int bm, int bn, int tid)
{
    __half* as = smem + s * LM_STG;
    __half* bs = as + LM_ASZ;
    const __half* Ag = A16 + (size_t)bm * HID + kt * LM_BK;
    const __half* Bg = B16 + (size_t)bn * HID + kt * LM_BK;
#pragma unroll
    for (int i = 0; i < 4; i++) {
        int c = tid + i * 256;
        int r = c >> 3, kc = (c & 7) * 8;
        cp_async16(as + r * LM_LDK + kc, Ag + (size_t)r * HID + kc);
    }
#pragma unroll
    for (int i = 0; i < 4; i++) {
        int c = tid + i * 256;
        int r = c >> 3, kc = (c & 7) * 8;
        cp_async16(bs + r * LM_LDK + kc, Bg + (size_t)r * HID + kc);
    }
}

__global__ void __launch_bounds__(256, 2) lm_fp16_kernel(
    const __half* __restrict__ A16, const __half* __restrict__ B16,
    float* __restrict__ C, float* __restrict__ pmax, float* __restrict__ psum)
{
    __half* smem = (__half*)dyn_smem;
    int tid = threadIdx.x;
    int lane = tid & 31, warp = tid >> 5;
    int wm = warp & 1, wn = warp >> 1;
    int gid = lane >> 2, tig = lane & 3;
    int bm = blockIdx.x * LM_BM;
    int bn = blockIdx.y * LM_BN;

    float acc[4][4][4];
#pragma unroll
    for (int i = 0; i < 4; i++)
#pragma unroll
        for (int j = 0; j < 4; j++)
#pragma unroll
            for (int q = 0; q < 4; q++) acc[i][j][q] = 0.f;

    uint32_t smem_u = (uint32_t)__cvta_generic_to_shared(smem);
    int a_off = (wm * 64 + (lane & 15)) * LM_LDK + ((lane >> 4) << 3);
    int b_off = (wn * 32 + ((lane >> 4) << 3) + (lane & 7)) * LM_LDK + (((lane >> 3) & 1) << 3);

    lm_load_stage(A16, B16, smem, 0, 0, bm, bn, tid); cp_commit();
    lm_load_stage(A16, B16, smem, 1, 1, bm, bn, tid); cp_commit();

    for (int kt = 0; kt < LM_KT; ++kt) {
        if (kt >= LM_KT - 2) cp_wait0(); else cp_wait1();
        __syncthreads();
        if (kt + 2 < LM_KT) {
            lm_load_stage(A16, B16, smem, kt + 2, (kt + 2) % 3, bm, bn, tid);
            cp_commit();
        }
        uint32_t a_base = smem_u + ((kt % 3) * LM_STG + a_off) * 2;
        uint32_t b_base = smem_u + ((kt % 3) * LM_STG + LM_ASZ + b_off) * 2;
#pragma unroll
        for (int kk = 0; kk < 4; kk++) {
            uint32_t af[4][4], bf4[2][4];
#pragma unroll
            for (int mi = 0; mi < 4; mi++)
                ldsm_x4(af[mi][0], af[mi][1], af[mi][2], af[mi][3],
                        a_base + (mi * 16 * LM_LDK + kk * 16) * 2);
#pragma unroll
            for (int np = 0; np < 2; np++)
                ldsm_x4(bf4[np][0], bf4[np][1], bf4[np][2], bf4[np][3],
                        b_base + (np * 16 * LM_LDK + kk * 16) * 2);
#pragma unroll
            for (int mi = 0; mi < 4; mi++) {
#pragma unroll
                for (int np = 0; np < 2; np++) {
                    mma_f16(acc[mi][2 * np],     af[mi], &bf4[np][0]);
                    mma_f16(acc[mi][2 * np + 1], af[mi], &bf4[np][2]);
                }
            }
        }
    }

    // ---- store logits (streaming: keep L2 for B tiles) ----
    float* Cb = C + (size_t)(bm + wm * 64) * VOC + bn + wn * 32;
#pragma unroll
    for (int mi = 0; mi < 4; mi++) {
#pragma unroll
        for (int ni = 0; ni < 4; ni++) {
            int r = mi * 16 + gid;
            int c = ni * 8 + tig * 2;
            st_cs_f2(Cb + (size_t)r * VOC + c,
                     make_float2(acc[mi][ni][0], acc[mi][ni][1]));
            st_cs_f2(Cb + (size_t)(r + 8) * VOC + c,
                     make_float2(acc[mi][ni][2], acc[mi][ni][3]));
        }
    }

    // ---- fused per-row softmax partials over this 128-col tile ----
    __syncthreads();
    float* pm = (float*)dyn_smem;
    float* ps = pm + 128 * 4;
#pragma unroll
    for (int mi = 0; mi < 4; mi++) {
#pragma unroll
        for (int h = 0; h < 2; h++) {
            float m0 = -1e30f;
#pragma unroll
            for (int ni = 0; ni < 4; ni++)
                m0 = fmaxf(m0, fmaxf(acc[mi][ni][2 * h], acc[mi][ni][2 * h + 1]));
            float s0 = 0.f;
#pragma unroll
            for (int ni = 0; ni < 4; ni++)
                s0 += __expf(acc[mi][ni][2 * h] - m0) + __expf(acc[mi][ni][2 * h + 1] - m0);
#pragma unroll
            for (int o = 1; o <= 2; o <<= 1) {
                float om = __shfl_xor_sync(0xffffffffu, m0, o);
                float os = __shfl_xor_sync(0xffffffffu, s0, o);
                float nm = fmaxf(m0, om);
                s0 = s0 * __expf(m0 - nm) + os * __expf(om - nm);
                m0 = nm;
            }
            if (tig == 0) {
                int lr = wm * 64 + mi * 16 + h * 8 + gid;
                pm[lr * 4 + wn] = m0;
                ps[lr * 4 + wn] = s0;
            }
        }
    }
    __syncthreads();
    if (tid < 128) {
        float m0 = pm[tid * 4], s0 = ps[tid * 4];
#pragma unroll
        for (int w = 1; w < 4; w++) {
            float om = pm[tid * 4 + w], os = ps[tid * 4 + w];
            float nm = fmaxf(m0, om);
            s0 = s0 * __expf(m0 - nm) + os * __expf(om - nm);
            m0 = nm;
        }
        size_t idx = (size_t)(bm + tid) * NT + blockIdx.y;
        pmax[idx] = m0;
        psum[idx] = s0;
    }
}

// ---------------- loss: merge per-tile partials (coalesced) ----------------
__global__ void __launch_bounds__(256) loss_reduce_kernel(
    const float* __restrict__ logits, const float* __restrict__ pmax,
    const float* __restrict__ psum, const void* __restrict__ labels,
    const float* __restrict__ mask, float* __restrict__ nll_out)
{
    int s = blockIdx.x;
    int tid = threadIdx.x;
    const float* pmr = pmax + (size_t)s * NT;
    const float* psr = psum + (size_t)s * NT;
    float m = -1e30f, su = 0.f;
    for (int nt = tid; nt < NT; nt += 256) {
        float om = pmr[nt];
        float os = psr[nt];
        float nm = fmaxf(m, om);
        su = su * __expf(m - nm) + os * __expf(om - nm);
        m = nm;
    }
#pragma unroll
    for (int o = 16; o > 0; o >>= 1) {
        float om = __shfl_xor_sync(0xffffffffu, m, o);
        float os = __shfl_xor_sync(0xffffffffu, su, o);
        float nm = fmaxf(m, om);
        su = su * __expf(m - nm) + os * __expf(om - nm);
        m = nm;
    }
    __shared__ float sm[8], ssu[8];
    if ((tid & 31) == 0) { sm[tid >> 5] = m; ssu[tid >> 5] = su; }
    __syncthreads();
    if (tid == 0) {
        float M0 = sm[0], S0 = ssu[0];
#pragma unroll
        for (int i = 1; i < 8; i++) {
            float nm = fmaxf(M0, sm[i]);
            S0 = S0 * __expf(M0 - nm) + ssu[i] * __expf(sm[i] - nm);
            M0 = nm;
        }
        bool is64 = detect_i64((const int*)labels);
        int lab = load_idx(labels, s + 1, is64);
        float lse = M0 + logf(S0);
        float nll = lse - logits[(size_t)s * VOC + lab];
        nll_out[s] = nll * mask[s + 1];
    }
}

__global__ void __launch_bounds__(256) final_kernel(
    const float* __restrict__ nll, const float* __restrict__ mask,
    float* __restrict__ out)
{
    __shared__ float red[8];
    int tid = threadIdx.x;
    float a = 0.f, b = 0.f;
    for (int j = tid; j < SEQ - 1; j += 256) { a += nll[j]; b += mask[j + 1]; }
    a = block_sum256(a, red);
    b = block_sum256(b, red);
    if (tid == 0) out[0] = a / (b + 1e-8f);
}

// ---------------- launch ----------------
extern "C" void kernel_launch(void* const* d_in, const int* in_sizes, int n_in,
                              void* d_out, int out_size)
{
    const float* hidden  = (const float*)d_in[0];
    const void*  ids     = d_in[1];
    const void*  labels  = d_in[2];
    const float* maskp   = (const float*)d_in[3];
    const float* embed_w = (const float*)d_in[4];
    const float* enorm   = (const float*)d_in[5];
    const float* hnorm   = (const float*)d_in[6];
    const float* ehw     = (const float*)d_in[7];
    const float* lnw     = (const float*)d_in[8];
    const float* nw      = (const float*)d_in[9];
    const float* lmw     = (const float*)d_in[10];
    float* logits = (float*)d_out;

    void *pch, *pwh, *pwl, *pp, *pa16, *pb16, *ppm, *pps, *pl;
    cudaGetSymbolAddress(&pch,  g_ch);
    cudaGetSymbolAddress(&pwh,  g_ewh);
    cudaGetSymbolAddress(&pwl,  g_ewl);
    cudaGetSymbolAddress(&pp,   g_proj);
    cudaGetSymbolAddress(&pa16, g_a16);
    cudaGetSymbolAddress(&pb16, g_b16);
    cudaGetSymbolAddress(&ppm,  g_pmax);
    cudaGetSymbolAddress(&pps,  g_psum);
    cudaGetSymbolAddress(&pl,   g_nll);

    cudaFuncSetAttribute(eh_fp16_kernel,
                         cudaFuncAttributeMaxDynamicSharedMemorySize, EH_SMEM);
    cudaFuncSetAttribute(lm_fp16_kernel,
                         cudaFuncAttributeMaxDynamicSharedMemorySize, LM_SMEM);

    // side streams + events (created lazily on the uncaptured correctness call)
    static cudaStream_t s2 = nullptr, s3 = nullptr;
    static cudaEvent_t evF = nullptr, evJ = nullptr, evP = nullptr;
    if (s2 == nullptr) {
        cudaStreamCreateWithFlags(&s2, cudaStreamNonBlocking);
        cudaStreamCreateWithFlags(&s3, cudaStreamNonBlocking);
        cudaEventCreateWithFlags(&evF, cudaEventDisableTiming);
        cudaEventCreateWithFlags(&evJ, cudaEventDisableTiming);
        cudaEventCreateWithFlags(&evP, cudaEventDisableTiming);
    }

    // fork
    cudaEventRecord(evF, 0);
    cudaStreamWaitEvent(s2, evF, 0);
    cudaStreamWaitEvent(s3, evF, 0);
    // s2: lm weight convert (long, overlaps entire eh chain)
    cvt_kernel<<<(int)(((size_t)VOC * HID) / (256 * 8)), 256, 0, s2>>>(lmw, (__half*)pb16);
    cudaEventRecord(evJ, s2);
    // s3: prep (independent of cvt_split)
    prep_kernel<<<SEQ, 256, 0, s3>>>(hidden, ids, embed_w, enorm, hnorm, (__half*)pch);
    cudaEventRecord(evP, s3);

    // main chain
    cvt_split_kernel<<<(int)(((size_t)HID * K2DIM) / (256 * 8)), 256>>>(
        ehw, (__half*)pwh, (__half*)pwl);
    cudaStreamWaitEvent(0, evP, 0);
    eh_fp16_kernel<<<dim3(SEQ / 64, HID / 128), 256, EH_SMEM>>>(
        (const __half*)pch, (const __half*)pwh, (const __half*)pwl, (float*)pp);
    norm2_kernel<<<SEQ, 256>>>((const float*)pp, lnw, nw, (__half*)pa16);

    // join: lm_head needs both g_a16 and g_b16
    cudaStreamWaitEvent(0, evJ, 0);
    lm_fp16_kernel<<<dim3(SEQ / LM_BM, NT), 256, LM_SMEM>>>(
        (const __half*)pa16, (const __half*)pb16, logits, (float*)ppm, (float*)pps);
    loss_reduce_kernel<<<SEQ - 1, 256>>>(logits, (const float*)ppm, (const float*)pps,
                                         labels, maskp, (float*)pl);
    final_kernel<<<1, 256>>>((const float*)pl, maskp, logits + (size_t)SEQ * VOC);
}

// round 16
// speedup vs baseline: 1.1029x; 1.0170x over previous
#include <cuda.h>
#include <cuda_runtime.h>
#include <cuda_fp16.h>
#include <cstdint>

#define SEQ   1024
#define HID   2048
#define K2DIM 4096
#define VOC   129280
#define EPSV  1e-6f
#define NT    (VOC / 128)          // 1010 N-tiles (128-wide)
#define NT_H  (NT / 2)             // 505 per lm launch
#define VOC_H (VOC / 2)            // 64640

// single dynamic-smem symbol shared by all kernels
extern __shared__ char dyn_smem[];

// ---------------- scratch (device globals, no allocation) ----------------
__device__ __half g_ch[SEQ * K2DIM];                // 8 MB combined hi (fp16)
__device__ __half g_ewh[(size_t)HID * K2DIM];       // 16 MB ehw hi
__device__ __half g_ewl[(size_t)HID * K2DIM];       // 16 MB ehw lo
__device__ float  g_proj[SEQ * HID];                // 8 MB
__device__ __half g_a16[SEQ * HID];                 // 4 MB (normed, fp16)
__device__ __half g_b16[(size_t)VOC * HID];         // 529 MB (lm_head_w fp16)
__device__ float  g_pmax[(size_t)SEQ * NT];         // [s][nt] coalesced for reduce
__device__ float  g_psum[(size_t)SEQ * NT];
__device__ float  g_nll[SEQ];

// ---------------- helpers ----------------
__device__ __forceinline__ unsigned h2_as_u32(__half2 h) {
    union { __half2 h; unsigned u; } c; c.h = h; return c.u;
}
__device__ __forceinline__ bool detect_i64(const int* w) {
    bool z = true;
#pragma unroll
    for (int j = 1; j < 32; j += 2) z = z && (w[j] == 0);
    return z;
}
__device__ __forceinline__ int load_idx(const void* p, int i, bool is64) {
    return is64 ? (int)((const long long*)p)[i] : ((const int*)p)[i];
}
__device__ __forceinline__ float block_sum256(float v, volatile float* red) {
#pragma unroll
    for (int o = 16; o > 0; o >>= 1) v += __shfl_xor_sync(0xffffffffu, v, o);
    if ((threadIdx.x & 31) == 0) red[threadIdx.x >> 5] = v;
    __syncthreads();
    float t = red[0] + red[1] + red[2] + red[3] + red[4] + red[5] + red[6] + red[7];
    __syncthreads();
    return t;
}

// .cg: bypass L1 (streamed GEMM operands have zero L1 reuse)
__device__ __forceinline__ void cp_async16(void* smem, const void* gmem) {
    unsigned sa = (unsigned)__cvta_generic_to_shared(smem);
    asm volatile("cp.async.cg.shared.global [%0], [%1], 16;" :: "r"(sa), "l"(gmem));
}
__device__ __forceinline__ void cp_commit() { asm volatile("cp.async.commit_group;"); }
__device__ __forceinline__ void cp_wait0() { asm volatile("cp.async.wait_group 0;"); }
__device__ __forceinline__ void cp_wait1() { asm volatile("cp.async.wait_group 1;"); }

__device__ __forceinline__ void ldsm_x4(uint32_t& r0, uint32_t& r1, uint32_t& r2,
                                        uint32_t& r3, uint32_t saddr) {
    asm volatile("ldmatrix.sync.aligned.m8n8.x4.shared.b16 {%0,%1,%2,%3}, [%4];"
        : "=r"(r0), "=r"(r1), "=r"(r2), "=r"(r3) : "r"(saddr));
}

__device__ __forceinline__ void mma_f16(float c[4], const uint32_t a[4], const uint32_t b[2]) {
    asm volatile(
        "mma.sync.aligned.m16n8k16.row.col.f32.f16.f16.f32 "
        "{%0,%1,%2,%3}, {%4,%5,%6,%7}, {%8,%9}, {%0,%1,%2,%3};"
        : "+f"(c[0]), "+f"(c[1]), "+f"(c[2]), "+f"(c[3])
        : "r"(a[0]), "r"(a[1]), "r"(a[2]), "r"(a[3]), "r"(b[0]), "r"(b[1]));
}

// streaming store (evict-first)
__device__ __forceinline__ void st_cs_f2(float* p, float2 v) {
    asm volatile("st.global.cs.v2.f32 [%0], {%1, %2};" :: "l"(p), "f"(v.x), "f"(v.y) : "memory");
}
__device__ __forceinline__ void st_cs_u4(void* p, uint4 v) {
    asm volatile("st.global.cs.v4.b32 [%0], {%1, %2, %3, %4};"
        :: "l"(p), "r"(v.x), "r"(v.y), "r"(v.z), "r"(v.w) : "memory");
}

// ---------------- kernel A: gather + enorm + hnorm + concat (fp16 hi) ----
__global__ void __launch_bounds__(256) prep_kernel(
    const float* __restrict__ hidden, const void* __restrict__ ids,
    const float* __restrict__ embed_w, const float* __restrict__ enorm_w,
    const float* __restrict__ hnorm_w, __half* __restrict__ chi)
{
    __shared__ float s_e[HID];
    __shared__ float s_h[HID];
    __shared__ float red[8];
    __shared__ int s_id;
    int tid = threadIdx.x, sid = blockIdx.x;
    if (tid == 0) {
        bool is64 = detect_i64((const int*)ids);
        s_id = load_idx(ids, sid, is64);
    }
    __syncthreads();
    const float* erow = embed_w + (size_t)s_id * HID;
    const float* hrow = hidden + (size_t)sid * HID;
    float se = 0.f, sh = 0.f;
    for (int j = tid; j < HID; j += 256) {
        float e = erow[j], h = hrow[j];
        s_e[j] = e; s_h[j] = h;
        se += e * e; sh += h * h;
    }
    float vse = block_sum256(se, red);
    float vsh = block_sum256(sh, red);
    float re = rsqrtf(vse / HID + EPSV);
    float rh = rsqrtf(vsh / HID + EPSV);
    __half* oh = chi + (size_t)sid * K2DIM;
    for (int j = tid; j < HID; j += 256) {
        oh[j]       = __float2half_rn(enorm_w[j] * s_e[j] * re);
        oh[HID + j] = __float2half_rn(hnorm_w[j] * s_h[j] * rh);
    }
}

// ---------------- double RMSNorm (ln then norm) -> fp16 output ----------------
__global__ void __launch_bounds__(256) norm2_kernel(
    const float* __restrict__ x, const float* __restrict__ lnw,
    const float* __restrict__ nw, __half* __restrict__ out)
{
    __shared__ float sx[HID];
    __shared__ float red[8];
    int sid = blockIdx.x, tid = threadIdx.x;
    const float* row = x + (size_t)sid * HID;
    float ss = 0.f;
    for (int j = tid; j < HID; j += 256) { float v = row[j]; sx[j] = v; ss += v * v; }
    float r1 = rsqrtf(block_sum256(ss, red) / HID + EPSV);
    float ss2 = 0.f;
    for (int j = tid; j < HID; j += 256) { float p = lnw[j] * sx[j] * r1; sx[j] = p; ss2 += p * p; }
    float r2 = rsqrtf(block_sum256(ss2, red) / HID + EPSV);
    __half* o = out + (size_t)sid * HID;
    for (int j = tid; j < HID; j += 256) o[j] = __float2half_rn(nw[j] * sx[j] * r2);
}

// ---------------- f32 -> f16 bulk convert (half-vocab chunk) ----------------
__global__ void __launch_bounds__(256) cvt_kernel(
    const float* __restrict__ in, __half* __restrict__ out)
{
    size_t i = ((size_t)blockIdx.x * 256 + threadIdx.x) * 8;
    float4 v0 = *reinterpret_cast<const float4*>(in + i);
    float4 v1 = *reinterpret_cast<const float4*>(in + i + 4);
    uint4 pk;
    pk.x = h2_as_u32(__floats2half2_rn(v0.x, v0.y));
    pk.y = h2_as_u32(__floats2half2_rn(v0.z, v0.w));
    pk.z = h2_as_u32(__floats2half2_rn(v1.x, v1.y));
    pk.w = h2_as_u32(__floats2half2_rn(v1.z, v1.w));
    st_cs_u4(out + i, pk);
}

// ---------------- f32 -> (hi, lo) fp16 split convert (ehw) ----------------
__global__ void __launch_bounds__(256) cvt_split_kernel(
    const float* __restrict__ in, __half* __restrict__ hi, __half* __restrict__ lo)
{
    size_t i = ((size_t)blockIdx.x * 256 + threadIdx.x) * 8;
    float v[8];
    *reinterpret_cast<float4*>(v)     = *reinterpret_cast<const float4*>(in + i);
    *reinterpret_cast<float4*>(v + 4) = *reinterpret_cast<const float4*>(in + i + 4);
    __half h[8], l[8];
#pragma unroll
    for (int j = 0; j < 8; j++) {
        h[j] = __float2half_rn(v[j]);
        l[j] = __float2half_rn(v[j] - __half2float(h[j]));
    }
    *reinterpret_cast<uint4*>(hi + i) = *reinterpret_cast<uint4*>(h);
    *reinterpret_cast<uint4*>(lo + i) = *reinterpret_cast<uint4*>(l);
}

// =======================================================================
// eh_proj: 2-term split-fp16 GEMM  proj = Ah*(Bh + Bl)  (R15 config)
// =======================================================================
#define EH_LDK  72
#define EH_A1   (64 * EH_LDK)
#define EH_B1   (128 * EH_LDK)
#define EH_STG  (EH_A1 + 2 * EH_B1)
#define EH_SMEM (2 * EH_STG * 2)          // 92160 B -> 2 CTAs/SM
#define EH_KT   (K2DIM / 64)              // 64

__device__ __forceinline__ void eh_load_stage(
    const __half* __restrict__ Ah,
    const __half* __restrict__ Bh, const __half* __restrict__ Bl,
    __half* smem, int kt, int s, int bm, int bn, int tid)
{
    __half* st = smem + s * EH_STG;
    size_t a0 = (size_t)bm * K2DIM + kt * 64;
    size_t b0 = (size_t)bn * K2DIM + kt * 64;
#pragma unroll
    for (int i = 0; i < 2; i++) {
        int c = tid + i * 256;
        int r = c >> 3, kc = (c & 7) * 8;
        cp_async16(st + r * EH_LDK + kc, Ah + a0 + (size_t)r * K2DIM + kc);
    }
#pragma unroll
    for (int i = 0; i < 4; i++) {
        int c = tid + i * 256;
        int r = c >> 3, kc = (c & 7) * 8;
        int so = r * EH_LDK + kc;
        cp_async16(st + EH_A1 + so,          Bh + b0 + (size_t)r * K2DIM + kc);
        cp_async16(st + EH_A1 + EH_B1 + so,  Bl + b0 + (size_t)r * K2DIM + kc);
    }
}

__global__ void __launch_bounds__(256, 2) eh_fp16_kernel(
    const __half* __restrict__ Ah,
    const __half* __restrict__ Bh, const __half* __restrict__ Bl,
    float* __restrict__ C)
{
    __half* smem = (__half*)dyn_smem;
    int tid = threadIdx.x;
    int lane = tid & 31, warp = tid >> 5;
    int wm = warp & 1, wn = warp >> 1;
    int gid = lane >> 2, tig = lane & 3;
    int bm = blockIdx.x * 64;
    int bn = blockIdx.y * 128;

    float acc[2][4][4];
#pragma unroll
    for (int i = 0; i < 2; i++)
#pragma unroll
        for (int j = 0; j < 4; j++)
#pragma unroll
            for (int q = 0; q < 4; q++) acc[i][j][q] = 0.f;

    uint32_t smem_u = (uint32_t)__cvta_generic_to_shared(smem);
    int a_off = (wm * 32 + (lane & 15)) * EH_LDK + ((lane >> 4) << 3);
    int b_off = (wn * 32 + ((lane >> 4) << 3) + (lane & 7)) * EH_LDK + (((lane >> 3) & 1) << 3);

    eh_load_stage(Ah, Bh, Bl, smem, 0, 0, bm, bn, tid); cp_commit();

    for (int kt = 0; kt < EH_KT; ++kt) {
        if (kt + 1 < EH_KT) {
            eh_load_stage(Ah, Bh, Bl, smem, kt + 1, (kt + 1) & 1, bm, bn, tid);
            cp_commit();
            cp_wait1();
        } else {
            cp_wait0();
        }
        __syncthreads();
        uint32_t stg = (kt & 1) * EH_STG;
        uint32_t ah_base = smem_u + (stg + a_off) * 2;
        uint32_t bh_base = smem_u + (stg + EH_A1 + b_off) * 2;
        uint32_t bl_base = bh_base + EH_B1 * 2;
#pragma unroll
        for (int kk = 0; kk < 4; kk++) {
            uint32_t ahf[2][4], bhf[2][4], blf[2][4];
#pragma unroll
            for (int mi = 0; mi < 2; mi++)
                ldsm_x4(ahf[mi][0], ahf[mi][1], ahf[mi][2], ahf[mi][3],
                        ah_base + (mi * 16 * EH_LDK + kk * 16) * 2);
#pragma unroll
            for (int np = 0; np < 2; np++) {
                ldsm_x4(bhf[np][0], bhf[np][1], bhf[np][2], bhf[np][3],
                        bh_base + (np * 16 * EH_LDK + kk * 16) * 2);
                ldsm_x4(blf[np][0], blf[np][1], blf[np][2], blf[np][3],
                        bl_base + (np * 16 * EH_LDK + kk * 16) * 2);
            }
#pragma unroll
            for (int mi = 0; mi < 2; mi++) {
#pragma unroll
                for (int np = 0; np < 2; np++) {
                    mma_f16(acc[mi][2 * np],     ahf[mi], &bhf[np][0]);
                    mma_f16(acc[mi][2 * np + 1], ahf[mi], &bhf[np][2]);
                    mma_f16(acc[mi][2 * np],     ahf[mi], &blf[np][0]);
                    mma_f16(acc[mi][2 * np + 1], ahf[mi], &blf[np][2]);
                }
            }
        }
        __syncthreads();
    }

    float* Cb = C + (size_t)(bm + wm * 32) * HID + bn + wn * 32;
#pragma unroll
    for (int mi = 0; mi < 2; mi++) {
#pragma unroll
        for (int ni = 0; ni < 4; ni++) {
            int r = mi * 16 + gid;
            int c = ni * 8 + tig * 2;
            float2 v0 = make_float2(acc[mi][ni][0], acc[mi][ni][1]);
            float2 v1 = make_float2(acc[mi][ni][2], acc[mi][ni][3]);
            *reinterpret_cast<float2*>(Cb + (size_t)r * HID + c) = v0;
            *reinterpret_cast<float2*>(Cb + (size_t)(r + 8) * HID + c) = v1;
        }
    }
}

// =======================================================================
// lm_head: fp16 mma.sync GEMM + fused softmax partials (R15 config)
//   nt0 = base N-tile (half-vocab split for cvt/GEMM pipelining).
// =======================================================================
#define LM_BM   128
#define LM_BN   128
#define LM_BK   64
#define LM_LDK  72
#define LM_ASZ  (LM_BM * LM_LDK)
#define LM_BSZ  (LM_BN * LM_LDK)
#define LM_STG  (LM_ASZ + LM_BSZ)
#define LM_SMEM (3 * LM_STG * 2)         // 110592 B
#define LM_KT   (HID / LM_BK)            // 32

__device__ __forceinline__ void lm_load_stage(
    const __half* __restrict__ A16, const __half* __restrict__ B16,
    __half* smem, int kt, int s, int bm, int bn, int tid)
{
    __half* as = smem + s * LM_STG;
    __half* bs = as + LM_ASZ;
    const __half* Ag = A16 + (size_t)bm * HID + kt * LM_BK;
    const __half* Bg = B16 + (size_t)bn * HID + kt * LM_BK;
#pragma unroll
    for (int i = 0; i < 4; i++) {
        int c = tid + i * 256;
        int r = c >> 3, kc = (c & 7) * 8;
        cp_async16(as + r * LM_LDK + kc, Ag + (size_t)r * HID + kc);
    }
#pragma unroll
    for (int i = 0; i < 4; i++) {
        int c = tid + i * 256;
        int r = c >> 3, kc = (c & 7) * 8;
        cp_async16(bs + r * LM_LDK + kc, Bg + (size_t)r * HID + kc);
    }
}

__global__ void __launch_bounds__(256, 2) lm_fp16_kernel(
    const __half* __restrict__ A16, const __half* __restrict__ B16,
    float* __restrict__ C, float* __restrict__ pmax, float* __restrict__ psum,
    int nt0)
{
    __half* smem = (__half*)dyn_smem;
    int tid = threadIdx.x;
    int lane = tid & 31, warp = tid >> 5;
    int wm = warp & 1, wn = warp >> 1;
    int gid = lane >> 2, tig = lane & 3;
    int nt = nt0 + blockIdx.y;
    int bm = blockIdx.x * LM_BM;
    int bn = nt * LM_BN;

    float acc[4][4][4];
#pragma unroll
    for (int i = 0; i < 4; i++)
#pragma unroll
        for (int j = 0; j < 4; j++)
#pragma unroll
            for (int q = 0; q < 4; q++) acc[i][j][q] = 0.f;

    uint32_t smem_u = (uint32_t)__cvta_generic_to_shared(smem);
    int a_off = (wm * 64 + (lane & 15)) * LM_LDK + ((lane >> 4) << 3);
    int b_off = (wn * 32 + ((lane >> 4) << 3) + (lane & 7)) * LM_LDK + (((lane >> 3) & 1) << 3);

    lm_load_stage(A16, B16, smem, 0, 0, bm, bn, tid); cp_commit();
    lm_load_stage(A16, B16, smem, 1, 1, bm, bn, tid); cp_commit();

    for (int kt = 0; kt < LM_KT; ++kt) {
        if (kt >= LM_KT - 2) cp_wait0(); else cp_wait1();
        __syncthreads();
        if (kt + 2 < LM_KT) {
            lm_load_stage(A16, B16, smem, kt + 2, (kt + 2) % 3, bm, bn, tid);
            cp_commit();
        }
        uint32_t a_base = smem_u + ((kt % 3) * LM_STG + a_off) * 2;
        uint32_t b_base = smem_u + ((kt % 3) * LM_STG + LM_ASZ + b_off) * 2;
#pragma unroll
        for (int kk = 0; kk < 4; kk++) {
            uint32_t af[4][4], bf4[2][4];
#pragma unroll
            for (int mi = 0; mi < 4; mi++)
                ldsm_x4(af[mi][0], af[mi][1], af[mi][2], af[mi][3],
                        a_base + (mi * 16 * LM_LDK + kk * 16) * 2);
#pragma unroll
            for (int np = 0; np < 2; np++)
                ldsm_x4(bf4[np][0], bf4[np][1], bf4[np][2], bf4[np][3],
                        b_base + (np * 16 * LM_LDK + kk * 16) * 2);
#pragma unroll
            for (int mi = 0; mi < 4; mi++) {
#pragma unroll
                for (int np = 0; np < 2; np++) {
                    mma_f16(acc[mi][2 * np],     af[mi], &bf4[np][0]);
                    mma_f16(acc[mi][2 * np + 1], af[mi], &bf4[np][2]);
                }
            }
        }
    }

    // ---- store logits (streaming) ----
    float* Cb = C + (size_t)(bm + wm * 64) * VOC + bn + wn * 32;
#pragma unroll
    for (int mi = 0; mi < 4; mi++) {
#pragma unroll
        for (int ni = 0; ni < 4; ni++) {
            int r = mi * 16 + gid;
            int c = ni * 8 + tig * 2;
            st_cs_f2(Cb + (size_t)r * VOC + c,
                     make_float2(acc[mi][ni][0], acc[mi][ni][1]));
            st_cs_f2(Cb + (size_t)(r + 8) * VOC + c,
                     make_float2(acc[mi][ni][2], acc[mi][ni][3]));
        }
    }

    // ---- fused per-row softmax partials over this 128-col tile ----
    __syncthreads();
    float* pm = (float*)dyn_smem;
    float* ps = pm + 128 * 4;
#pragma unroll
    for (int mi = 0; mi < 4; mi++) {
#pragma unroll
        for (int h = 0; h < 2; h++) {
            float m0 = -1e30f;
#pragma unroll
            for (int ni = 0; ni < 4; ni++)
                m0 = fmaxf(m0, fmaxf(acc[mi][ni][2 * h], acc[mi][ni][2 * h + 1]));
            float s0 = 0.f;
#pragma unroll
            for (int ni = 0; ni < 4; ni++)
                s0 += __expf(acc[mi][ni][2 * h] - m0) + __expf(acc[mi][ni][2 * h + 1] - m0);
#pragma unroll
            for (int o = 1; o <= 2; o <<= 1) {
                float om = __shfl_xor_sync(0xffffffffu, m0, o);
                float os = __shfl_xor_sync(0xffffffffu, s0, o);
                float nm = fmaxf(m0, om);
                s0 = s0 * __expf(m0 - nm) + os * __expf(om - nm);
                m0 = nm;
            }
            if (tig == 0) {
                int lr = wm * 64 + mi * 16 + h * 8 + gid;
                pm[lr * 4 + wn] = m0;
                ps[lr * 4 + wn] = s0;
            }
        }
    }
    __syncthreads();
    if (tid < 128) {
        float m0 = pm[tid * 4], s0 = ps[tid * 4];
#pragma unroll
        for (int w = 1; w < 4; w++) {
            float om = pm[tid * 4 + w], os = ps[tid * 4 + w];
            float nm = fmaxf(m0, om);
            s0 = s0 * __expf(m0 - nm) + os * __expf(om - nm);
            m0 = nm;
        }
        size_t idx = (size_t)(bm + tid) * NT + nt;
        pmax[idx] = m0;
        psum[idx] = s0;
    }
}

// ---------------- loss: merge per-tile partials (coalesced) ----------------
__global__ void __launch_bounds__(256) loss_reduce_kernel(
    const float* __restrict__ logits, const float* __restrict__ pmax,
    const float* __restrict__ psum, const void* __restrict__ labels,
    const float* __restrict__ mask, float* __restrict__ nll_out)
{
    int s = blockIdx.x;
    int tid = threadIdx.x;
    const float* pmr = pmax + (size_t)s * NT;
    const float* psr = psum + (size_t)s * NT;
    float m = -1e30f, su = 0.f;
    for (int nt = tid; nt < NT; nt += 256) {
        float om = pmr[nt];
        float os = psr[nt];
        float nm = fmaxf(m, om);
        su = su * __expf(m - nm) + os * __expf(om - nm);
        m = nm;
    }
#pragma unroll
    for (int o = 16; o > 0; o >>= 1) {
        float om = __shfl_xor_sync(0xffffffffu, m, o);
        float os = __shfl_xor_sync(0xffffffffu, su, o);
        float nm = fmaxf(m, om);
        su = su * __expf(m - nm) + os * __expf(om - nm);
        m = nm;
    }
    __shared__ float sm[8], ssu[8];
    if ((tid & 31) == 0) { sm[tid >> 5] = m; ssu[tid >> 5] = su; }
    __syncthreads();
    if (tid == 0) {
        float M0 = sm[0], S0 = ssu[0];
#pragma unroll
        for (int i = 1; i < 8; i++) {
            float nm = fmaxf(M0, sm[i]);
            S0 = S0 * __expf(M0 - nm) + ssu[i] * __expf(sm[i] - nm);
            M0 = nm;
        }
        bool is64 = detect_i64((const int*)labels);
        int lab = load_idx(labels, s + 1, is64);
        float lse = M0 + logf(S0);
        float nll = lse - logits[(size_t)s * VOC + lab];
        nll_out[s] = nll * mask[s + 1];
    }
}

__global__ void __launch_bounds__(256) final_kernel(
    const float* __restrict__ nll, const float* __restrict__ mask,
    float* __restrict__ out)
{
    __shared__ float red[8];
    int tid = threadIdx.x;
    float a = 0.f, b = 0.f;
    for (int j = tid; j < SEQ - 1; j += 256) { a += nll[j]; b += mask[j + 1]; }
    a = block_sum256(a, red);
    b = block_sum256(b, red);
    if (tid == 0) out[0] = a / (b + 1e-8f);
}

// ---------------- launch ----------------
extern "C" void kernel_launch(void* const* d_in, const int* in_sizes, int n_in,
                              void* d_out, int out_size)
{
    const float* hidden  = (const float*)d_in[0];
    const void*  ids     = d_in[1];
    const void*  labels  = d_in[2];
    const float* maskp   = (const float*)d_in[3];
    const float* embed_w = (const float*)d_in[4];
    const float* enorm   = (const float*)d_in[5];
    const float* hnorm   = (const float*)d_in[6];
    const float* ehw     = (const float*)d_in[7];
    const float* lnw     = (const float*)d_in[8];
    const float* nw      = (const float*)d_in[9];
    const float* lmw     = (const float*)d_in[10];
    float* logits = (float*)d_out;

    void *pch, *pwh, *pwl, *pp, *pa16, *pb16, *ppm, *pps, *pl;
    cudaGetSymbolAddress(&pch,  g_ch);
    cudaGetSymbolAddress(&pwh,  g_ewh);
    cudaGetSymbolAddress(&pwl,  g_ewl);
    cudaGetSymbolAddress(&pp,   g_proj);
    cudaGetSymbolAddress(&pa16, g_a16);
    cudaGetSymbolAddress(&pb16, g_b16);
    cudaGetSymbolAddress(&ppm,  g_pmax);
    cudaGetSymbolAddress(&pps,  g_psum);
    cudaGetSymbolAddress(&pl,   g_nll);

    cudaFuncSetAttribute(eh_fp16_kernel,
                         cudaFuncAttributeMaxDynamicSharedMemorySize, EH_SMEM);
    cudaFuncSetAttribute(lm_fp16_kernel,
                         cudaFuncAttributeMaxDynamicSharedMemorySize, LM_SMEM);

    // side streams + events (created lazily on the uncaptured correctness call)
    static cudaStream_t s2 = nullptr, s3 = nullptr;
    static cudaEvent_t evF = nullptr, evJ1 = nullptr, evJ2 = nullptr,
                       evP = nullptr, evN = nullptr, evL2 = nullptr;
    if (s2 == nullptr) {
        cudaStreamCreateWithFlags(&s2, cudaStreamNonBlocking);
        cudaStreamCreateWithFlags(&s3, cudaStreamNonBlocking);
        cudaEventCreateWithFlags(&evF,  cudaEventDisableTiming);
        cudaEventCreateWithFlags(&evJ1, cudaEventDisableTiming);
        cudaEventCreateWithFlags(&evJ2, cudaEventDisableTiming);
        cudaEventCreateWithFlags(&evP,  cudaEventDisableTiming);
        cudaEventCreateWithFlags(&evN,  cudaEventDisableTiming);
        cudaEventCreateWithFlags(&evL2, cudaEventDisableTiming);
    }

    const int CVT_GRID_H = (int)(((size_t)VOC_H * HID) / (256 * 8));

    // fork
    cudaEventRecord(evF, 0);
    cudaStreamWaitEvent(s2, evF, 0);
    cudaStreamWaitEvent(s3, evF, 0);
    // s2: lm weight convert in two half-vocab chunks
    cvt_kernel<<<CVT_GRID_H, 256, 0, s2>>>(lmw, (__half*)pb16);
    cudaEventRecord(evJ1, s2);
    cvt_kernel<<<CVT_GRID_H, 256, 0, s2>>>(lmw + (size_t)VOC_H * HID,
                                           (__half*)pb16 + (size_t)VOC_H * HID);
    cudaEventRecord(evJ2, s2);
    // s3: prep (independent of cvt_split)
    prep_kernel<<<SEQ, 256, 0, s3>>>(hidden, ids, embed_w, enorm, hnorm, (__half*)pch);
    cudaEventRecord(evP, s3);

    // main chain
    cvt_split_kernel<<<(int)(((size_t)HID * K2DIM) / (256 * 8)), 256>>>(
        ehw, (__half*)pwh, (__half*)pwl);
    cudaStreamWaitEvent(0, evP, 0);
    eh_fp16_kernel<<<dim3(SEQ / 64, HID / 128), 256, EH_SMEM>>>(
        (const __half*)pch, (const __half*)pwh, (const __half*)pwl, (float*)pp);
    norm2_kernel<<<SEQ, 256>>>((const float*)pp, lnw, nw, (__half*)pa16);
    cudaEventRecord(evN, 0);

    // lm half 1: needs A + first half of B
    cudaStreamWaitEvent(0, evJ1, 0);
    lm_fp16_kernel<<<dim3(SEQ / LM_BM, NT_H), 256, LM_SMEM>>>(
        (const __half*)pa16, (const __half*)pb16, logits,
        (float*)ppm, (float*)pps, 0);
    // lm half 2 on s3: needs A (evN) + second half of B (evJ2); overlaps half 1's tail
    cudaStreamWaitEvent(s3, evN, 0);
    cudaStreamWaitEvent(s3, evJ2, 0);
    lm_fp16_kernel<<<dim3(SEQ / LM_BM, NT_H), 256, LM_SMEM, s3>>>(
        (const __half*)pa16, (const __half*)pb16, logits,
        (float*)ppm, (float*)pps, NT_H);
    cudaEventRecord(evL2, s3);

    // loss waits for both halves
    cudaStreamWaitEvent(0, evL2, 0);
    loss_reduce_kernel<<<SEQ - 1, 256>>>(logits, (const float*)ppm, (const float*)pps,
                                         labels, maskp, (float*)pl);
    final_kernel<<<1, 256>>>((const float*)pl, maskp, logits + (size_t)SEQ * VOC);
}

// round 17
// speedup vs baseline: 1.1311x; 1.0255x over previous
#include <cuda.h>
#include <cuda_runtime.h>
#include <cuda_fp16.h>
#include <cstdint>

#define SEQ   1024
#define HID   2048
#define K2DIM 4096
#define VOC   129280
#define EPSV  1e-6f
#define NT    (VOC / 128)          // 1010 N-tiles (128-wide)
#define NT_H  (NT / 2)             // 505 per lm launch
#define VOC_H (VOC / 2)            // 64640

// single dynamic-smem symbol shared by all kernels
extern __shared__ char dyn_smem[];

// ---------------- scratch (device globals, no allocation) ----------------
__device__ __half g_ch[SEQ * K2DIM];                // 8 MB combined (fp16)
__device__ __half g_ewh[(size_t)HID * K2DIM];       // 16 MB ehw fp16
__device__ float  g_proj[SEQ * HID];                // 8 MB
__device__ __half g_a16[SEQ * HID];                 // 4 MB (normed, fp16)
__device__ __half g_b16[(size_t)VOC * HID];         // 529 MB (lm_head_w fp16)
__device__ float  g_pmax[(size_t)SEQ * NT];         // [s][nt] coalesced for reduce
__device__ float  g_psum[(size_t)SEQ * NT];
__device__ float  g_nll[SEQ];

// ---------------- helpers ----------------
__device__ __forceinline__ unsigned h2_as_u32(__half2 h) {
    union { __half2 h; unsigned u; } c; c.h = h; return c.u;
}
__device__ __forceinline__ bool detect_i64(const int* w) {
    bool z = true;
#pragma unroll
    for (int j = 1; j < 32; j += 2) z = z && (w[j] == 0);
    return z;
}
__device__ __forceinline__ int load_idx(const void* p, int i, bool is64) {
    return is64 ? (int)((const long long*)p)[i] : ((const int*)p)[i];
}
__device__ __forceinline__ float block_sum256(float v, volatile float* red) {
#pragma unroll
    for (int o = 16; o > 0; o >>= 1) v += __shfl_xor_sync(0xffffffffu, v, o);
    if ((threadIdx.x & 31) == 0) red[threadIdx.x >> 5] = v;
    __syncthreads();
    float t = red[0] + red[1] + red[2] + red[3] + red[4] + red[5] + red[6] + red[7];
    __syncthreads();
    return t;
}

// .cg: bypass L1 (streamed GEMM operands have zero L1 reuse)
__device__ __forceinline__ void cp_async16(void* smem, const void* gmem) {
    unsigned sa = (unsigned)__cvta_generic_to_shared(smem);
    asm volatile("cp.async.cg.shared.global [%0], [%1], 16;" :: "r"(sa), "l"(gmem));
}
__device__ __forceinline__ void cp_commit() { asm volatile("cp.async.commit_group;"); }
__device__ __forceinline__ void cp_wait0() { asm volatile("cp.async.wait_group 0;"); }
__device__ __forceinline__ void cp_wait1() { asm volatile("cp.async.wait_group 1;"); }

__device__ __forceinline__ void ldsm_x4(uint32_t& r0, uint32_t& r1, uint32_t& r2,
                                        uint32_t& r3, uint32_t saddr) {
    asm volatile("ldmatrix.sync.aligned.m8n8.x4.shared.b16 {%0,%1,%2,%3}, [%4];"
        : "=r"(r0), "=r"(r1), "=r"(r2), "=r"(r3) : "r"(saddr));
}

__device__ __forceinline__ void mma_f16(float c[4], const uint32_t a[4], const uint32_t b[2]) {
    asm volatile(
        "mma.sync.aligned.m16n8k16.row.col.f32.f16.f16.f32 "
        "{%0,%1,%2,%3}, {%4,%5,%6,%7}, {%8,%9}, {%0,%1,%2,%3};"
        : "+f"(c[0]), "+f"(c[1]), "+f"(c[2]), "+f"(c[3])
        : "r"(a[0]), "r"(a[1]), "r"(a[2]), "r"(a[3]), "r"(b[0]), "r"(b[1]));
}

// streaming store (evict-first)
__device__ __forceinline__ void st_cs_f2(float* p, float2 v) {
    asm volatile("st.global.cs.v2.f32 [%0], {%1, %2};" :: "l"(p), "f"(v.x), "f"(v.y) : "memory");
}
__device__ __forceinline__ void st_cs_u4(void* p, uint4 v) {
    asm volatile("st.global.cs.v4.b32 [%0], {%1, %2, %3, %4};"
        :: "l"(p), "r"(v.x), "r"(v.y), "r"(v.z), "r"(v.w) : "memory");
}

// ---------------- kernel A: gather + enorm + hnorm + concat (fp16) ----
__global__ void __launch_bounds__(256) prep_kernel(
    const float* __restrict__ hidden, const void* __restrict__ ids,
    const float* __restrict__ embed_w, const float* __restrict__ enorm_w,
    const float* __restrict__ hnorm_w, __half* __restrict__ chi)
{
    __shared__ float s_e[HID];
    __shared__ float s_h[HID];
    __shared__ float red[8];
    __shared__ int s_id;
    int tid = threadIdx.x, sid = blockIdx.x;
    if (tid == 0) {
        bool is64 = detect_i64((const int*)ids);
        s_id = load_idx(ids, sid, is64);
    }
    __syncthreads();
    const float* erow = embed_w + (size_t)s_id * HID;
    const float* hrow = hidden + (size_t)sid * HID;
    float se = 0.f, sh = 0.f;
    for (int j = tid; j < HID; j += 256) {
        float e = erow[j], h = hrow[j];
        s_e[j] = e; s_h[j] = h;
        se += e * e; sh += h * h;
    }
    float vse = block_sum256(se, red);
    float vsh = block_sum256(sh, red);
    float re = rsqrtf(vse / HID + EPSV);
    float rh = rsqrtf(vsh / HID + EPSV);
    __half* oh = chi + (size_t)sid * K2DIM;
    for (int j = tid; j < HID; j += 256) {
        oh[j]       = __float2half_rn(enorm_w[j] * s_e[j] * re);
        oh[HID + j] = __float2half_rn(hnorm_w[j] * s_h[j] * rh);
    }
}

// ---------------- double RMSNorm (ln then norm) -> fp16 output ----------------
__global__ void __launch_bounds__(256) norm2_kernel(
    const float* __restrict__ x, const float* __restrict__ lnw,
    const float* __restrict__ nw, __half* __restrict__ out)
{
    __shared__ float sx[HID];
    __shared__ float red[8];
    int sid = blockIdx.x, tid = threadIdx.x;
    const float* row = x + (size_t)sid * HID;
    float ss = 0.f;
    for (int j = tid; j < HID; j += 256) { float v = row[j]; sx[j] = v; ss += v * v; }
    float r1 = rsqrtf(block_sum256(ss, red) / HID + EPSV);
    float ss2 = 0.f;
    for (int j = tid; j < HID; j += 256) { float p = lnw[j] * sx[j] * r1; sx[j] = p; ss2 += p * p; }
    float r2 = rsqrtf(block_sum256(ss2, red) / HID + EPSV);
    __half* o = out + (size_t)sid * HID;
    for (int j = tid; j < HID; j += 256) o[j] = __float2half_rn(nw[j] * sx[j] * r2);
}

// ---------------- f32 -> f16 bulk convert ----------------
__global__ void __launch_bounds__(256) cvt_kernel(
    const float* __restrict__ in, __half* __restrict__ out)
{
    size_t i = ((size_t)blockIdx.x * 256 + threadIdx.x) * 8;
    float4 v0 = *reinterpret_cast<const float4*>(in + i);
    float4 v1 = *reinterpret_cast<const float4*>(in + i + 4);
    uint4 pk;
    pk.x = h2_as_u32(__floats2half2_rn(v0.x, v0.y));
    pk.y = h2_as_u32(__floats2half2_rn(v0.z, v0.w));
    pk.z = h2_as_u32(__floats2half2_rn(v1.x, v1.y));
    pk.w = h2_as_u32(__floats2half2_rn(v1.z, v1.w));
    st_cs_u4(out + i, pk);
}

// =======================================================================
// eh_proj: plain fp16 GEMM  proj = Ah*Bh
//   CTA 64x128, 8 warps (2M x 4N, 32x32), BK=64, 2-stage, 2 CTAs/SM.
// =======================================================================
#define EH_LDK  72
#define EH_A1   (64 * EH_LDK)             // 4608 halves (A)
#define EH_B1   (128 * EH_LDK)            // 9216 halves (B)
#define EH_STG  (EH_A1 + EH_B1)           // 13824 halves = 27648 B
#define EH_SMEM (2 * EH_STG * 2)          // 55296 B
#define EH_KT   (K2DIM / 64)              // 64

__device__ __forceinline__ void eh_load_stage(
    const __half* __restrict__ Ah, const __half* __restrict__ Bh,
    __half* smem, int kt, int s, int bm, int bn, int tid)
{
    __half* st = smem + s * EH_STG;
    size_t a0 = (size_t)bm * K2DIM + kt * 64;
    size_t b0 = (size_t)bn * K2DIM + kt * 64;
#pragma unroll
    for (int i = 0; i < 2; i++) {          // A: 512 chunks
        int c = tid + i * 256;
        int r = c >> 3, kc = (c & 7) * 8;
        cp_async16(st + r * EH_LDK + kc, Ah + a0 + (size_t)r * K2DIM + kc);
    }
#pragma unroll
    for (int i = 0; i < 4; i++) {          // B: 1024 chunks
        int c = tid + i * 256;
        int r = c >> 3, kc = (c & 7) * 8;
        cp_async16(st + EH_A1 + r * EH_LDK + kc, Bh + b0 + (size_t)r * K2DIM + kc);
    }
}

__global__ void __launch_bounds__(256, 2) eh_fp16_kernel(
    const __half* __restrict__ Ah, const __half* __restrict__ Bh,
    float* __restrict__ C)
{
    __half* smem = (__half*)dyn_smem;
    int tid = threadIdx.x;
    int lane = tid & 31, warp = tid >> 5;
    int wm = warp & 1, wn = warp >> 1;
    int gid = lane >> 2, tig = lane & 3;
    int bm = blockIdx.x * 64;
    int bn = blockIdx.y * 128;

    float acc[2][4][4];
#pragma unroll
    for (int i = 0; i < 2; i++)
#pragma unroll
        for (int j = 0; j < 4; j++)
#pragma unroll
            for (int q = 0; q < 4; q++) acc[i][j][q] = 0.f;

    uint32_t smem_u = (uint32_t)__cvta_generic_to_shared(smem);
    int a_off = (wm * 32 + (lane & 15)) * EH_LDK + ((lane >> 4) << 3);
    int b_off = (wn * 32 + ((lane >> 4) << 3) + (lane & 7)) * EH_LDK + (((lane >> 3) & 1) << 3);

    eh_load_stage(Ah, Bh, smem, 0, 0, bm, bn, tid); cp_commit();

    for (int kt = 0; kt < EH_KT; ++kt) {
        if (kt + 1 < EH_KT) {
            eh_load_stage(Ah, Bh, smem, kt + 1, (kt + 1) & 1, bm, bn, tid);
            cp_commit();
            cp_wait1();
        } else {
            cp_wait0();
        }
        __syncthreads();
        uint32_t stg = (kt & 1) * EH_STG;
        uint32_t ah_base = smem_u + (stg + a_off) * 2;
        uint32_t bh_base = smem_u + (stg + EH_A1 + b_off) * 2;
#pragma unroll
        for (int kk = 0; kk < 4; kk++) {
            uint32_t ahf[2][4], bhf[2][4];
#pragma unroll
            for (int mi = 0; mi < 2; mi++)
                ldsm_x4(ahf[mi][0], ahf[mi][1], ahf[mi][2], ahf[mi][3],
                        ah_base + (mi * 16 * EH_LDK + kk * 16) * 2);
#pragma unroll
            for (int np = 0; np < 2; np++)
                ldsm_x4(bhf[np][0], bhf[np][1], bhf[np][2], bhf[np][3],
                        bh_base + (np * 16 * EH_LDK + kk * 16) * 2);
#pragma unroll
            for (int mi = 0; mi < 2; mi++) {
#pragma unroll
                for (int np = 0; np < 2; np++) {
                    mma_f16(acc[mi][2 * np],     ahf[mi], &bhf[np][0]);
                    mma_f16(acc[mi][2 * np + 1], ahf[mi], &bhf[np][2]);
                }
            }
        }
        __syncthreads();
    }

    float* Cb = C + (size_t)(bm + wm * 32) * HID + bn + wn * 32;
#pragma unroll
    for (int mi = 0; mi < 2; mi++) {
#pragma unroll
        for (int ni = 0; ni < 4; ni++) {
            int r = mi * 16 + gid;
            int c = ni * 8 + tig * 2;
            float2 v0 = make_float2(acc[mi][ni][0], acc[mi][ni][1]);
            float2 v1 = make_float2(acc[mi][ni][2], acc[mi][ni][3]);
            *reinterpret_cast<float2*>(Cb + (size_t)r * HID + c) = v0;
            *reinterpret_cast<float2*>(Cb + (size_t)(r + 8) * HID + c) = v1;
        }
    }
}

// =======================================================================
// lm_head: fp16 mma.sync GEMM + fused softmax partials (R16 config)
// =======================================================================
#define LM_BM   128
#define LM_BN   128
#define LM_BK   64
#define LM_LDK  72
#define LM_ASZ  (LM_BM * LM_LDK)
#define LM_BSZ  (LM_BN * LM_LDK)
#define LM_STG  (LM_ASZ + LM_BSZ)
#define LM_SMEM (3 * LM_STG * 2)         // 110592 B
#define LM_KT   (HID / LM_BK)            // 32

__device__ __forceinline__ void lm_load_stage(
    const __half* __restrict__ A16, const __half* __restrict__ B16,
    __half* smem, int kt, int s, int bm, int bn, int tid)
{
    __half* as = smem + s * LM_STG;
    __half* bs = as + LM_ASZ;
    const __half* Ag = A16 + (size_t)bm * HID + kt * LM_BK;
    const __half* Bg = B16 + (size_t)bn * HID + kt * LM_BK;
#pragma unroll
    for (int i = 0; i < 4; i++) {
        int c = tid + i * 256;
        int r = c >> 3, kc = (c & 7) * 8;
        cp_async16(as + r * LM_LDK + kc, Ag + (size_t)r * HID + kc);
    }
#pragma unroll
    for (int i = 0; i < 4; i++) {
        int c = tid + i * 256;
        int r = c >> 3, kc = (c & 7) * 8;
        cp_async16(bs + r * LM_LDK + kc, Bg + (size_t)r * HID + kc);
    }
}

__global__ void __launch_bounds__(256, 2) lm_fp16_kernel(
    const __half* __restrict__ A16, const __half* __restrict__ B16,
    float* __restrict__ C, float* __restrict__ pmax, float* __restrict__ psum,
    int nt0)
{
    __half* smem = (__half*)dyn_smem;
    int tid = threadIdx.x;
    int lane = tid & 31, warp = tid >> 5;
    int wm = warp & 1, wn = warp >> 1;
    int gid = lane >> 2, tig = lane & 3;
    int nt = nt0 + blockIdx.y;
    int bm = blockIdx.x * LM_BM;
    int bn = nt * LM_BN;

    float acc[4][4][4];
#pragma unroll
    for (int i = 0; i < 4; i++)
#pragma unroll
        for (int j = 0; j < 4; j++)
#pragma unroll
            for (int q = 0; q < 4; q++) acc[i][j][q] = 0.f;

    uint32_t smem_u = (uint32_t)__cvta_generic_to_shared(smem);
    int a_off = (wm * 64 + (lane & 15)) * LM_LDK + ((lane >> 4) << 3);
    int b_off = (wn * 32 + ((lane >> 4) << 3) + (lane & 7)) * LM_LDK + (((lane >> 3) & 1) << 3);

    lm_load_stage(A16, B16, smem, 0, 0, bm, bn, tid); cp_commit();
    lm_load_stage(A16, B16, smem, 1, 1, bm, bn, tid); cp_commit();

    for (int kt = 0; kt < LM_KT; ++kt) {
        if (kt >= LM_KT - 2) cp_wait0(); else cp_wait1();
        __syncthreads();
        if (kt + 2 < LM_KT) {
            lm_load_stage(A16, B16, smem, kt + 2, (kt + 2) % 3, bm, bn, tid);
            cp_commit();
        }
        uint32_t a_base = smem_u + ((kt % 3) * LM_STG + a_off) * 2;
        uint32_t b_base = smem_u + ((kt % 3) * LM_STG + LM_ASZ + b_off) * 2;
#pragma unroll
        for (int kk = 0; kk < 4; kk++) {
            uint32_t af[4][4], bf4[2][4];
#pragma unroll
            for (int mi = 0; mi < 4; mi++)
                ldsm_x4(af[mi][0], af[mi][1], af[mi][2], af[mi][3],
                        a_base + (mi * 16 * LM_LDK + kk * 16) * 2);
#pragma unroll
            for (int np = 0; np < 2; np++)
                ldsm_x4(bf4[np][0], bf4[np][1], bf4[np][2], bf4[np][3],
                        b_base + (np * 16 * LM_LDK + kk * 16) * 2);
#pragma unroll
            for (int mi = 0; mi < 4; mi++) {
#pragma unroll
                for (int np = 0; np < 2; np++) {
                    mma_f16(acc[mi][2 * np],     af[mi], &bf4[np][0]);
                    mma_f16(acc[mi][2 * np + 1], af[mi], &bf4[np][2]);
                }
            }
        }
    }

    // ---- store logits (streaming) ----
    float* Cb = C + (size_t)(bm + wm * 64) * VOC + bn + wn * 32;
#pragma unroll
    for (int mi = 0; mi < 4; mi++) {
#pragma unroll
        for (int ni = 0; ni < 4; ni++) {
            int r = mi * 16 + gid;
            int c = ni * 8 + tig * 2;
            st_cs_f2(Cb + (size_t)r * VOC + c,
                     make_float2(acc[mi][ni][0], acc[mi][ni][1]));
            st_cs_f2(Cb + (size_t)(r + 8) * VOC + c,
                     make_float2(acc[mi][ni][2], acc[mi][ni][3]));
        }
    }

    // ---- fused per-row softmax partials over this 128-col tile ----
    __syncthreads();
    float* pm = (float*)dyn_smem;
    float* ps = pm + 128 * 4;
#pragma unroll
    for (int mi = 0; mi < 4; mi++) {
#pragma unroll
        for (int h = 0; h < 2; h++) {
            float m0 = -1e30f;
#pragma unroll
            for (int ni = 0; ni < 4; ni++)
                m0 = fmaxf(m0, fmaxf(acc[mi][ni][2 * h], acc[mi][ni][2 * h + 1]));
            float s0 = 0.f;
#pragma unroll
            for (int ni = 0; ni < 4; ni++)
                s0 += __expf(acc[mi][ni][2 * h] - m0) + __expf(acc[mi][ni][2 * h + 1] - m0);
#pragma unroll
            for (int o = 1; o <= 2; o <<= 1) {
                float om = __shfl_xor_sync(0xffffffffu, m0, o);
                float os = __shfl_xor_sync(0xffffffffu, s0, o);
                float nm = fmaxf(m0, om);
                s0 = s0 * __expf(m0 - nm) + os * __expf(om - nm);
                m0 = nm;
            }
            if (tig == 0) {
                int lr = wm * 64 + mi * 16 + h * 8 + gid;
                pm[lr * 4 + wn] = m0;
                ps[lr * 4 + wn] = s0;
            }
        }
    }
    __syncthreads();
    if (tid < 128) {
        float m0 = pm[tid * 4], s0 = ps[tid * 4];
#pragma unroll
        for (int w = 1; w < 4; w++) {
            float om = pm[tid * 4 + w], os = ps[tid * 4 + w];
            float nm = fmaxf(m0, om);
            s0 = s0 * __expf(m0 - nm) + os * __expf(om - nm);
            m0 = nm;
        }
        size_t idx = (size_t)(bm + tid) * NT + nt;
        pmax[idx] = m0;
        psum[idx] = s0;
    }
}

// ---------------- loss: merge per-tile partials (coalesced) ----------------
__global__ void __launch_bounds__(256) loss_reduce_kernel(
    const float* __restrict__ logits, const float* __restrict__ pmax,
    const float* __restrict__ psum, const void* __restrict__ labels,
    const float* __restrict__ mask, float* __restrict__ nll_out)
{
    int s = blockIdx.x;
    int tid = threadIdx.x;
    const float* pmr = pmax + (size_t)s * NT;
    const float* psr = psum + (size_t)s * NT;
    float m = -1e30f, su = 0.f;
    for (int nt = tid; nt < NT; nt += 256) {
        float om = pmr[nt];
        float os = psr[nt];
        float nm = fmaxf(m, om);
        su = su * __expf(m - nm) + os * __expf(om - nm);
        m = nm;
    }
#pragma unroll
    for (int o = 16; o > 0; o >>= 1) {
        float om = __shfl_xor_sync(0xffffffffu, m, o);
        float os = __shfl_xor_sync(0xffffffffu, su, o);
        float nm = fmaxf(m, om);
        su = su * __expf(m - nm) + os * __expf(om - nm);
        m = nm;
    }
    __shared__ float sm[8], ssu[8];
    if ((tid & 31) == 0) { sm[tid >> 5] = m; ssu[tid >> 5] = su; }
    __syncthreads();
    if (tid == 0) {
        float M0 = sm[0], S0 = ssu[0];
#pragma unroll
        for (int i = 1; i < 8; i++) {
            float nm = fmaxf(M0, sm[i]);
            S0 = S0 * __expf(M0 - nm) + ssu[i] * __expf(sm[i] - nm);
            M0 = nm;
        }
        bool is64 = detect_i64((const int*)labels);
        int lab = load_idx(labels, s + 1, is64);
        float lse = M0 + logf(S0);
        float nll = lse - logits[(size_t)s * VOC + lab];
        nll_out[s] = nll * mask[s + 1];
    }
}

__global__ void __launch_bounds__(256) final_kernel(
    const float* __restrict__ nll, const float* __restrict__ mask,
    float* __restrict__ out)
{
    __shared__ float red[8];
    int tid = threadIdx.x;
    float a = 0.f, b = 0.f;
    for (int j = tid; j < SEQ - 1; j += 256) { a += nll[j]; b += mask[j + 1]; }
    a = block_sum256(a, red);
    b = block_sum256(b, red);
    if (tid == 0) out[0] = a / (b + 1e-8f);
}

// ---------------- launch ----------------
extern "C" void kernel_launch(void* const* d_in, const int* in_sizes, int n_in,
                              void* d_out, int out_size)
{
    const float* hidden  = (const float*)d_in[0];
    const void*  ids     = d_in[1];
    const void*  labels  = d_in[2];
    const float* maskp   = (const float*)d_in[3];
    const float* embed_w = (const float*)d_in[4];
    const float* enorm   = (const float*)d_in[5];
    const float* hnorm   = (const float*)d_in[6];
    const float* ehw     = (const float*)d_in[7];
    const float* lnw     = (const float*)d_in[8];
    const float* nw      = (const float*)d_in[9];
    const float* lmw     = (const float*)d_in[10];
    float* logits = (float*)d_out;

    void *pch, *pwh, *pp, *pa16, *pb16, *ppm, *pps, *pl;
    cudaGetSymbolAddress(&pch,  g_ch);
    cudaGetSymbolAddress(&pwh,  g_ewh);
    cudaGetSymbolAddress(&pp,   g_proj);
    cudaGetSymbolAddress(&pa16, g_a16);
    cudaGetSymbolAddress(&pb16, g_b16);
    cudaGetSymbolAddress(&ppm,  g_pmax);
    cudaGetSymbolAddress(&pps,  g_psum);
    cudaGetSymbolAddress(&pl,   g_nll);

    cudaFuncSetAttribute(eh_fp16_kernel,
                         cudaFuncAttributeMaxDynamicSharedMemorySize, EH_SMEM);
    cudaFuncSetAttribute(lm_fp16_kernel,
                         cudaFuncAttributeMaxDynamicSharedMemorySize, LM_SMEM);

    // side streams + events (created lazily on the uncaptured correctness call)
    static cudaStream_t s2 = nullptr, s3 = nullptr;
    static cudaEvent_t evF = nullptr, evJ1 = nullptr, evJ2 = nullptr,
                       evP = nullptr, evN = nullptr, evL2 = nullptr;
    if (s2 == nullptr) {
        cudaStreamCreateWithFlags(&s2, cudaStreamNonBlocking);
        cudaStreamCreateWithFlags(&s3, cudaStreamNonBlocking);
        cudaEventCreateWithFlags(&evF,  cudaEventDisableTiming);
        cudaEventCreateWithFlags(&evJ1, cudaEventDisableTiming);
        cudaEventCreateWithFlags(&evJ2, cudaEventDisableTiming);
        cudaEventCreateWithFlags(&evP,  cudaEventDisableTiming);
        cudaEventCreateWithFlags(&evN,  cudaEventDisableTiming);
        cudaEventCreateWithFlags(&evL2, cudaEventDisableTiming);
    }

    const int CVT_GRID_H = (int)(((size_t)VOC_H * HID) / (256 * 8));

    // fork
    cudaEventRecord(evF, 0);
    cudaStreamWaitEvent(s2, evF, 0);
    cudaStreamWaitEvent(s3, evF, 0);
    // s2: lm weight convert in two half-vocab chunks
    cvt_kernel<<<CVT_GRID_H, 256, 0, s2>>>(lmw, (__half*)pb16);
    cudaEventRecord(evJ1, s2);
    cvt_kernel<<<CVT_GRID_H, 256, 0, s2>>>(lmw + (size_t)VOC_H * HID,
                                           (__half*)pb16 + (size_t)VOC_H * HID);
    cudaEventRecord(evJ2, s2);
    // s3: prep (independent of ehw convert)
    prep_kernel<<<SEQ, 256, 0, s3>>>(hidden, ids, embed_w, enorm, hnorm, (__half*)pch);
    cudaEventRecord(evP, s3);

    // main chain
    cvt_kernel<<<(int)(((size_t)HID * K2DIM) / (256 * 8)), 256>>>(ehw, (__half*)pwh);
    cudaStreamWaitEvent(0, evP, 0);
    eh_fp16_kernel<<<dim3(SEQ / 64, HID / 128), 256, EH_SMEM>>>(
        (const __half*)pch, (const __half*)pwh, (float*)pp);
    norm2_kernel<<<SEQ, 256>>>((const float*)pp, lnw, nw, (__half*)pa16);
    cudaEventRecord(evN, 0);

    // lm half 1: needs A + first half of B
    cudaStreamWaitEvent(0, evJ1, 0);
    lm_fp16_kernel<<<dim3(SEQ / LM_BM, NT_H), 256, LM_SMEM>>>(
        (const __half*)pa16, (const __half*)pb16, logits,
        (float*)ppm, (float*)pps, 0);
    // lm half 2 on s3: needs A (evN) + second half of B (evJ2); overlaps half 1's tail
    cudaStreamWaitEvent(s3, evN, 0);
    cudaStreamWaitEvent(s3, evJ2, 0);
    lm_fp16_kernel<<<dim3(SEQ / LM_BM, NT_H), 256, LM_SMEM, s3>>>(
        (const __half*)pa16, (const __half*)pb16, logits,
        (float*)ppm, (float*)pps, NT_H);
    cudaEventRecord(evL2, s3);

    // loss waits for both halves
    cudaStreamWaitEvent(0, evL2, 0);
    loss_reduce_kernel<<<SEQ - 1, 256>>>(logits, (const float*)ppm, (const float*)pps,
                                         labels, maskp, (float*)pl);
    final_kernel<<<1, 256>>>((const float*)pl, maskp, logits + (size_t)SEQ * VOC);
}